// round 1
// baseline (speedup 1.0000x reference)
#include <cuda_runtime.h>
#include <cstdint>

#define G 4
#define NN 50000
#define EE 800000
#define F_IN 64
#define HID 128
#define OUT 64

// ---- scratch (static device allocations, allowed) ----
__device__ int   d_deg [G * NN];
__device__ float d_dinv[G * NN];
__device__ float d_h1  [(size_t)G * NN * HID];   // (x@W1)*dinv  (layer1 pre-scaled)
__device__ float d_acc1[(size_t)G * NN * HID];   // scatter accumulator -> out1 (in place)
__device__ float d_h2  [(size_t)G * NN * OUT];   // (out1@W2)*dinv

__device__ __forceinline__ void red4(float4* p, float4 v) {
    asm volatile("red.global.add.v4.f32 [%0], {%1, %2, %3, %4};"
                 :: "l"(p), "f"(v.x), "f"(v.y), "f"(v.z), "f"(v.w) : "memory");
}

__device__ __forceinline__ float elu1(float v) {
    return v > 0.f ? v : expm1f(v);
}

// ---------------- zero scratch + output ----------------
__global__ void zero_all_kernel(float* __restrict__ out) {
    const size_t stride = (size_t)gridDim.x * blockDim.x;
    size_t tid = (size_t)blockIdx.x * blockDim.x + threadIdx.x;
    float4 z = make_float4(0.f, 0.f, 0.f, 0.f);
    float4* a = (float4*)d_acc1;
    const size_t n1 = (size_t)G * NN * HID / 4;
    for (size_t i = tid; i < n1; i += stride) a[i] = z;
    float4* o = (float4*)out;
    const size_t n2 = (size_t)G * NN * OUT / 4;
    for (size_t i = tid; i < n2; i += stride) o[i] = z;
    const size_t n3 = (size_t)G * NN;
    for (size_t i = tid; i < n3; i += stride) d_deg[i] = 0;
}

// ---------------- degree ----------------
__global__ void degree_kernel(const int* __restrict__ ei) {
    int idx = blockIdx.x * blockDim.x + threadIdx.x;
    if (idx >= G * EE) return;
    int g = idx / EE;
    int e = idx - g * EE;
    int dst = ei[(size_t)g * 2 * EE + EE + e];
    atomicAdd(&d_deg[g * NN + dst], 1);
}

__global__ void dinv_kernel() {
    int idx = blockIdx.x * blockDim.x + threadIdx.x;
    if (idx >= G * NN) return;
    d_dinv[idx] = rsqrtf((float)(d_deg[idx] + 1));
}

// ---------------- GEMM1: h1 = (x @ W1) * dinv[row] ----------------
// block: 128 threads (one per HID col), 32 rows/block
__global__ __launch_bounds__(128) void gemm1_kernel(const float* __restrict__ x,
                                                    const float* __restrict__ W1) {
    const int g = blockIdx.y;
    const int base = blockIdx.x * 32;
    __shared__ float xs[32 * F_IN];

    const float* xg = x + (size_t)g * NN * F_IN;
    int limit = (NN - base) * F_IN; if (limit > 32 * F_IN) limit = 32 * F_IN;
    for (int i = threadIdx.x; i < 32 * F_IN; i += 128)
        xs[i] = (i < limit) ? xg[(size_t)base * F_IN + i] : 0.f;

    float w[F_IN];
    const float* Wg = W1 + (size_t)g * F_IN * HID + threadIdx.x;
#pragma unroll
    for (int k = 0; k < F_IN; k++) w[k] = Wg[k * HID];
    __syncthreads();

    int rmax = NN - base; if (rmax > 32) rmax = 32;
    for (int r = 0; r < rmax; r++) {
        const float4* xv = (const float4*)(xs + r * F_IN);
        float acc = 0.f;
#pragma unroll
        for (int q = 0; q < F_IN / 4; q++) {
            float4 v = xv[q];
            acc = fmaf(v.x, w[4 * q + 0], acc);
            acc = fmaf(v.y, w[4 * q + 1], acc);
            acc = fmaf(v.z, w[4 * q + 2], acc);
            acc = fmaf(v.w, w[4 * q + 3], acc);
        }
        int row = base + r;
        d_h1[(size_t)g * NN * HID + (size_t)row * HID + threadIdx.x] =
            acc * d_dinv[g * NN + row];
    }
}

// ---------------- scatter layer1: warp per edge, v4 red ----------------
__global__ __launch_bounds__(256) void scatter1_kernel(const int* __restrict__ ei, int g) {
    int warp = (blockIdx.x * 256 + threadIdx.x) >> 5;
    int lane = threadIdx.x & 31;
    if (warp >= EE) return;
    const int* eg = ei + (size_t)g * 2 * EE;
    int src = eg[warp];
    int dst = eg[EE + warp];
    const float4* hv = (const float4*)(d_h1 + (size_t)g * NN * HID);
    float4 v = hv[(size_t)src * (HID / 4) + lane];
    float4* av = (float4*)(d_acc1 + (size_t)g * NN * HID);
    red4(&av[(size_t)dst * (HID / 4) + lane], v);
}

// ---------------- finalize1: acc1 <- elu(dinv*(acc1+h1)+b1) ----------------
__global__ void finalize1_kernel(const float* __restrict__ b1) {
    int idx = blockIdx.x * blockDim.x + threadIdx.x;  // over G*N*HID/4
    if (idx >= G * NN * (HID / 4)) return;
    int row = idx >> 5;               // HID/4 = 32
    int q = idx & 31;
    int g = row / NN;
    float dv = d_dinv[row];
    float4 a = ((float4*)d_acc1)[idx];
    float4 h = ((const float4*)d_h1)[idx];
    float4 b = ((const float4*)(b1 + g * HID))[q];
    float4 r;
    r.x = elu1(fmaf(a.x + h.x, dv, b.x));
    r.y = elu1(fmaf(a.y + h.y, dv, b.y));
    r.z = elu1(fmaf(a.z + h.z, dv, b.z));
    r.w = elu1(fmaf(a.w + h.w, dv, b.w));
    ((float4*)d_acc1)[idx] = r;
}

// ---------------- GEMM2: h2 = (out1 @ W2) * dinv[row]  (K=128 -> OUT=64) ----
// 128 threads: f = t&63 (out col), half = t>>6 (K half); 16 rows/block
__global__ __launch_bounds__(128) void gemm2_kernel(const float* __restrict__ W2) {
    const int g = blockIdx.y;
    const int base = blockIdx.x * 16;
    const int f = threadIdx.x & 63;
    const int half = threadIdx.x >> 6;
    __shared__ float xs[16 * HID];
    __shared__ float part[128];

    const float* in = d_acc1 + (size_t)g * NN * HID;
    int limit = (NN - base) * HID; if (limit > 16 * HID) limit = 16 * HID;
    for (int i = threadIdx.x; i < 16 * HID; i += 128)
        xs[i] = (i < limit) ? in[(size_t)base * HID + i] : 0.f;

    float w[64];
    const float* Wg = W2 + (size_t)g * HID * OUT + (size_t)(half * 64) * OUT + f;
#pragma unroll
    for (int k = 0; k < 64; k++) w[k] = Wg[k * OUT];
    __syncthreads();

    for (int r = 0; r < 16; r++) {
        const float4* xv = (const float4*)(xs + r * HID + half * 64);
        float acc = 0.f;
#pragma unroll
        for (int q = 0; q < 16; q++) {
            float4 v = xv[q];
            acc = fmaf(v.x, w[4 * q + 0], acc);
            acc = fmaf(v.y, w[4 * q + 1], acc);
            acc = fmaf(v.z, w[4 * q + 2], acc);
            acc = fmaf(v.w, w[4 * q + 3], acc);
        }
        part[threadIdx.x] = acc;
        __syncthreads();
        int row = base + r;
        if (threadIdx.x < 64 && row < NN) {
            float s = part[threadIdx.x] + part[threadIdx.x + 64];
            d_h2[(size_t)g * NN * OUT + (size_t)row * OUT + f] =
                s * d_dinv[g * NN + row];
        }
        __syncthreads();
    }
}

// ---------------- scatter layer2: 16 threads per edge, v4 red ----------------
__global__ __launch_bounds__(256) void scatter2_kernel(const int* __restrict__ ei, int g,
                                                       float* __restrict__ out) {
    int t = blockIdx.x * 256 + threadIdx.x;
    int e = t >> 4;
    int q = t & 15;
    if (e >= EE) return;
    const int* eg = ei + (size_t)g * 2 * EE;
    int src = eg[e];
    int dst = eg[EE + e];
    const float4* hv = (const float4*)(d_h2 + (size_t)g * NN * OUT);
    float4 v = hv[(size_t)src * (OUT / 4) + q];
    float4* ov = (float4*)out;
    red4(&ov[((size_t)g * NN + dst) * (OUT / 4) + q], v);
}

// ---------------- finalize2: out <- elu(dinv*(out+h2)+b2) ----------------
__global__ void finalize2_kernel(const float* __restrict__ b2, float* __restrict__ out) {
    int idx = blockIdx.x * blockDim.x + threadIdx.x;  // over G*N*OUT/4
    if (idx >= G * NN * (OUT / 4)) return;
    int row = idx >> 4;               // OUT/4 = 16
    int q = idx & 15;
    int g = row / NN;
    float dv = d_dinv[row];
    float4 a = ((float4*)out)[idx];
    float4 h = ((const float4*)d_h2)[idx];
    float4 b = ((const float4*)(b2 + g * OUT))[q];
    float4 r;
    r.x = elu1(fmaf(a.x + h.x, dv, b.x));
    r.y = elu1(fmaf(a.y + h.y, dv, b.y));
    r.z = elu1(fmaf(a.z + h.z, dv, b.z));
    r.w = elu1(fmaf(a.w + h.w, dv, b.w));
    ((float4*)out)[idx] = r;
}

extern "C" void kernel_launch(void* const* d_in, const int* in_sizes, int n_in,
                              void* d_out, int out_size) {
    const float* x  = (const float*)d_in[0];
    const int*   ei = (const int*)  d_in[1];
    const float* W1 = (const float*)d_in[2];
    const float* b1 = (const float*)d_in[3];
    const float* W2 = (const float*)d_in[4];
    const float* b2 = (const float*)d_in[5];
    float* out = (float*)d_out;

    zero_all_kernel<<<4096, 256>>>(out);
    degree_kernel<<<(G * EE + 255) / 256, 256>>>(ei);
    dinv_kernel<<<(G * NN + 255) / 256, 256>>>();

    gemm1_kernel<<<dim3((NN + 31) / 32, G), 128>>>(x, W1);
    for (int g = 0; g < G; g++)
        scatter1_kernel<<<(EE * 32 + 255) / 256, 256>>>(ei, g);
    finalize1_kernel<<<(G * NN * (HID / 4) + 255) / 256, 256>>>(b1);

    gemm2_kernel<<<dim3((NN + 15) / 16, G), 128>>>(W2);
    for (int g = 0; g < G; g++)
        scatter2_kernel<<<(EE * 16 + 255) / 256, 256>>>(ei, g, out);
    finalize2_kernel<<<(G * NN * (OUT / 4) + 255) / 256, 256>>>(b2, out);
}

// round 2
// speedup vs baseline: 1.5460x; 1.5460x over previous
#include <cuda_runtime.h>
#include <cstdint>

#define G 4
#define NN 50000
#define EE 800000
#define F_IN 64
#define HID 128
#define OUT 64
#define NTOT (G * NN)
#define SCAN_BS 1024
#define SCAN_NB ((NTOT + SCAN_BS - 1) / SCAN_BS)   // 196

// ---- scratch ----
__device__ int   d_deg   [NTOT];
__device__ int   d_scan  [NTOT];
__device__ int   d_start [NTOT];
__device__ int   d_cursor[NTOT];
__device__ int   d_bsum  [SCAN_NB];
__device__ int   d_boff  [SCAN_NB];
__device__ int   d_csr   [(size_t)G * EE];
__device__ float d_dinv  [NTOT];
__device__ float d_xp    [(size_t)NTOT * F_IN];   // x * dinv, then reused? (kept)
__device__ float d_agg   [(size_t)NTOT * F_IN];   // dinv*(sum + self)
__device__ float d_H1    [(size_t)NTOT * HID];    // elu(agg@W1+b1)
__device__ float d_h2    [(size_t)NTOT * OUT];    // (H1@W2)*dinv

__device__ __forceinline__ float elu1(float v) {
    return v > 0.f ? v : expm1f(v);
}

// ---------------- zero degree ----------------
__global__ void zero_deg_kernel() {
    int i = blockIdx.x * blockDim.x + threadIdx.x;
    if (i < NTOT) d_deg[i] = 0;
}

// ---------------- degree ----------------
__global__ void degree_kernel(const int* __restrict__ ei) {
    int idx = blockIdx.x * blockDim.x + threadIdx.x;
    if (idx >= G * EE) return;
    int g = idx / EE;
    int e = idx - g * EE;
    int dst = ei[(size_t)g * 2 * EE + EE + e];
    atomicAdd(&d_deg[g * NN + dst], 1);
}

__global__ void dinv_kernel() {
    int i = blockIdx.x * blockDim.x + threadIdx.x;
    if (i >= NTOT) return;
    d_dinv[i] = rsqrtf((float)(d_deg[i] + 1));
}

// ---------------- scan (exclusive prefix over d_deg) ----------------
__global__ __launch_bounds__(256) void scan1_kernel() {
    __shared__ int sh[256];
    int b = blockIdx.x, t = threadIdx.x;
    int base = b * SCAN_BS + t * 4;
    int v[4]; int s = 0;
#pragma unroll
    for (int k = 0; k < 4; k++) {
        int i = base + k;
        v[k] = (i < NTOT) ? d_deg[i] : 0;
        s += v[k];
    }
    sh[t] = s;
    __syncthreads();
    for (int off = 1; off < 256; off <<= 1) {
        int add = (t >= off) ? sh[t - off] : 0;
        __syncthreads();
        sh[t] += add;
        __syncthreads();
    }
    int run = sh[t] - s;   // exclusive prefix of this thread within block
#pragma unroll
    for (int k = 0; k < 4; k++) {
        run += v[k];
        if (base + k < NTOT) d_scan[base + k] = run;   // inclusive
    }
    if (t == 255) d_bsum[b] = sh[255];
}

__global__ __launch_bounds__(256) void scan2_kernel() {
    __shared__ int sh[256];
    int t = threadIdx.x;
    int v = (t < SCAN_NB) ? d_bsum[t] : 0;
    sh[t] = v;
    __syncthreads();
    for (int off = 1; off < 256; off <<= 1) {
        int add = (t >= off) ? sh[t - off] : 0;
        __syncthreads();
        sh[t] += add;
        __syncthreads();
    }
    if (t < SCAN_NB) d_boff[t] = sh[t] - v;   // exclusive block offsets
}

__global__ void scan3_kernel() {
    int i = blockIdx.x * blockDim.x + threadIdx.x;
    if (i >= NTOT) return;
    int excl = d_scan[i] - d_deg[i] + d_boff[i / SCAN_BS];
    d_start[i]  = excl;
    d_cursor[i] = excl;
}

// ---------------- CSR fill ----------------
__global__ void fill_kernel(const int* __restrict__ ei) {
    int idx = blockIdx.x * blockDim.x + threadIdx.x;
    if (idx >= G * EE) return;
    int g = idx / EE;
    int e = idx - g * EE;
    int src = ei[(size_t)g * 2 * EE + e];
    int dst = ei[(size_t)g * 2 * EE + EE + e];
    int slot = atomicAdd(&d_cursor[g * NN + dst], 1);
    d_csr[slot] = src;
}

// ---------------- x' = x * dinv[row] ----------------
__global__ void scale_x_kernel(const float* __restrict__ x) {
    int idx = blockIdx.x * blockDim.x + threadIdx.x;   // over NTOT*16
    int row = idx >> 4;
    float4 v = ((const float4*)x)[idx];
    float dv = d_dinv[row];
    v.x *= dv; v.y *= dv; v.z *= dv; v.w *= dv;
    ((float4*)d_xp)[idx] = v;
}

// ---------------- gather layer1: agg[i] = dinv[i]*(sum x'[s] + x'[i]) --------
// 16 threads per node row (64 floats = 16 float4). grid*block == NTOT*16 exactly.
__global__ __launch_bounds__(256) void gather1_kernel() {
    int tid = blockIdx.x * 256 + threadIdx.x;
    int i = tid >> 4;
    int lane = tid & 15;
    int g = i / NN;
    int start = d_start[i];
    int d = d_deg[i];
    const float4* xv = (const float4*)d_xp;
    float4 acc = xv[(size_t)i * 16 + lane];   // self loop
    int rowbase = g * NN;
    for (int c = 0; c < d; c += 16) {
        int mi = c + lane;
        int ms = (mi < d) ? d_csr[start + mi] : 0;
        int cnt = min(16, d - c);
        for (int j = 0; j < cnt; j++) {
            int src = __shfl_sync(0xffffffffu, ms, j, 16);
            float4 v = xv[(size_t)(rowbase + src) * 16 + lane];
            acc.x += v.x; acc.y += v.y; acc.z += v.z; acc.w += v.w;
        }
    }
    float dv = d_dinv[i];
    acc.x *= dv; acc.y *= dv; acc.z *= dv; acc.w *= dv;
    ((float4*)d_agg)[(size_t)i * 16 + lane] = acc;
}

// ---------------- gemm1: H1 = elu(agg @ W1 + b1) ----------------
// 128 threads = 1 per HID col, 32 rows/block
__global__ __launch_bounds__(128) void gemm1_kernel(const float* __restrict__ W1,
                                                    const float* __restrict__ b1) {
    const int g = blockIdx.y;
    const int base = blockIdx.x * 32;
    const int t = threadIdx.x;
    __shared__ float xs[32 * F_IN];

    const float4* src = (const float4*)(d_agg + ((size_t)g * NN + base) * F_IN);
    int limit4 = (NN - base) * (F_IN / 4); if (limit4 > 512) limit4 = 512;
    float4 z = make_float4(0.f, 0.f, 0.f, 0.f);
    for (int i = t; i < 512; i += 128)
        ((float4*)xs)[i] = (i < limit4) ? src[i] : z;

    float w[F_IN];
    const float* Wg = W1 + (size_t)g * F_IN * HID + t;
#pragma unroll
    for (int k = 0; k < F_IN; k++) w[k] = Wg[k * HID];
    float bb = b1[g * HID + t];
    __syncthreads();

    int rmax = NN - base; if (rmax > 32) rmax = 32;
    for (int r = 0; r < rmax; r++) {
        const float4* xv = (const float4*)(xs + r * F_IN);
        float a0 = 0.f, a1 = 0.f, a2 = 0.f, a3 = 0.f;
#pragma unroll
        for (int q = 0; q < F_IN / 16; q++) {
            float4 v0 = xv[4 * q + 0];
            float4 v1 = xv[4 * q + 1];
            float4 v2 = xv[4 * q + 2];
            float4 v3 = xv[4 * q + 3];
            a0 = fmaf(v0.x, w[16*q+0], a0); a0 = fmaf(v0.y, w[16*q+1], a0);
            a0 = fmaf(v0.z, w[16*q+2], a0); a0 = fmaf(v0.w, w[16*q+3], a0);
            a1 = fmaf(v1.x, w[16*q+4], a1); a1 = fmaf(v1.y, w[16*q+5], a1);
            a1 = fmaf(v1.z, w[16*q+6], a1); a1 = fmaf(v1.w, w[16*q+7], a1);
            a2 = fmaf(v2.x, w[16*q+8], a2); a2 = fmaf(v2.y, w[16*q+9], a2);
            a2 = fmaf(v2.z, w[16*q+10], a2); a2 = fmaf(v2.w, w[16*q+11], a2);
            a3 = fmaf(v3.x, w[16*q+12], a3); a3 = fmaf(v3.y, w[16*q+13], a3);
            a3 = fmaf(v3.z, w[16*q+14], a3); a3 = fmaf(v3.w, w[16*q+15], a3);
        }
        float s = (a0 + a1) + (a2 + a3);
        int row = base + r;
        d_H1[((size_t)g * NN + row) * HID + t] = elu1(s + bb);
    }
}

// ---------------- gemm2: h2 = (H1 @ W2) * dinv[row] ----------------
// 128 threads: f = t>>1 (out col), half = t&1 (K half); 32 rows/block
__global__ __launch_bounds__(128) void gemm2_kernel(const float* __restrict__ W2) {
    const int g = blockIdx.y;
    const int base = blockIdx.x * 32;
    const int t = threadIdx.x;
    const int f = t >> 1;
    const int half = t & 1;
    __shared__ float xs[32 * HID];   // 16KB

    const float4* src = (const float4*)(d_H1 + ((size_t)g * NN + base) * HID);
    int limit4 = (NN - base) * (HID / 4); if (limit4 > 1024) limit4 = 1024;
    float4 z = make_float4(0.f, 0.f, 0.f, 0.f);
    for (int i = t; i < 1024; i += 128)
        ((float4*)xs)[i] = (i < limit4) ? src[i] : z;

    float w[64];
    const float* Wg = W2 + (size_t)g * HID * OUT + (size_t)(half * 64) * OUT + f;
#pragma unroll
    for (int k = 0; k < 64; k++) w[k] = Wg[k * OUT];
    __syncthreads();

    int rmax = NN - base; if (rmax > 32) rmax = 32;
    for (int r = 0; r < rmax; r++) {
        const float4* xv = (const float4*)(xs + r * HID + half * 64);
        float a0 = 0.f, a1 = 0.f, a2 = 0.f, a3 = 0.f;
#pragma unroll
        for (int q = 0; q < 4; q++) {
            float4 v0 = xv[4 * q + 0];
            float4 v1 = xv[4 * q + 1];
            float4 v2 = xv[4 * q + 2];
            float4 v3 = xv[4 * q + 3];
            a0 = fmaf(v0.x, w[16*q+0], a0); a0 = fmaf(v0.y, w[16*q+1], a0);
            a0 = fmaf(v0.z, w[16*q+2], a0); a0 = fmaf(v0.w, w[16*q+3], a0);
            a1 = fmaf(v1.x, w[16*q+4], a1); a1 = fmaf(v1.y, w[16*q+5], a1);
            a1 = fmaf(v1.z, w[16*q+6], a1); a1 = fmaf(v1.w, w[16*q+7], a1);
            a2 = fmaf(v2.x, w[16*q+8], a2); a2 = fmaf(v2.y, w[16*q+9], a2);
            a2 = fmaf(v2.z, w[16*q+10], a2); a2 = fmaf(v2.w, w[16*q+11], a2);
            a3 = fmaf(v3.x, w[16*q+12], a3); a3 = fmaf(v3.y, w[16*q+13], a3);
            a3 = fmaf(v3.z, w[16*q+14], a3); a3 = fmaf(v3.w, w[16*q+15], a3);
        }
        float s = (a0 + a1) + (a2 + a3);
        s += __shfl_xor_sync(0xffffffffu, s, 1);
        int row = base + r;
        if (half == 0 && row < NN) {
            d_h2[((size_t)g * NN + row) * OUT + f] = s * d_dinv[g * NN + row];
        }
    }
}

// ---------------- gather layer2 + epilogue: out = elu(dinv*(sum+self)+b2) ----
__global__ __launch_bounds__(256) void gather2_kernel(const float* __restrict__ b2,
                                                      float* __restrict__ out) {
    int tid = blockIdx.x * 256 + threadIdx.x;
    int i = tid >> 4;
    int lane = tid & 15;
    int g = i / NN;
    int start = d_start[i];
    int d = d_deg[i];
    const float4* hv = (const float4*)d_h2;
    float4 acc = hv[(size_t)i * 16 + lane];   // self loop
    int rowbase = g * NN;
    for (int c = 0; c < d; c += 16) {
        int mi = c + lane;
        int ms = (mi < d) ? d_csr[start + mi] : 0;
        int cnt = min(16, d - c);
        for (int j = 0; j < cnt; j++) {
            int src = __shfl_sync(0xffffffffu, ms, j, 16);
            float4 v = hv[(size_t)(rowbase + src) * 16 + lane];
            acc.x += v.x; acc.y += v.y; acc.z += v.z; acc.w += v.w;
        }
    }
    float dv = d_dinv[i];
    float4 b = ((const float4*)(b2 + g * OUT))[lane];
    float4 r;
    r.x = elu1(fmaf(acc.x, dv, b.x));
    r.y = elu1(fmaf(acc.y, dv, b.y));
    r.z = elu1(fmaf(acc.z, dv, b.z));
    r.w = elu1(fmaf(acc.w, dv, b.w));
    ((float4*)out)[(size_t)i * 16 + lane] = r;
}

extern "C" void kernel_launch(void* const* d_in, const int* in_sizes, int n_in,
                              void* d_out, int out_size) {
    const float* x  = (const float*)d_in[0];
    const int*   ei = (const int*)  d_in[1];
    const float* W1 = (const float*)d_in[2];
    const float* b1 = (const float*)d_in[3];
    const float* W2 = (const float*)d_in[4];
    const float* b2 = (const float*)d_in[5];
    float* out = (float*)d_out;

    zero_deg_kernel<<<(NTOT + 255) / 256, 256>>>();
    degree_kernel<<<(G * EE + 255) / 256, 256>>>(ei);
    dinv_kernel<<<(NTOT + 255) / 256, 256>>>();

    scan1_kernel<<<SCAN_NB, 256>>>();
    scan2_kernel<<<1, 256>>>();
    scan3_kernel<<<(NTOT + 255) / 256, 256>>>();
    fill_kernel<<<(G * EE + 255) / 256, 256>>>(ei);

    scale_x_kernel<<<(NTOT * 16) / 256, 256>>>(x);
    gather1_kernel<<<(NTOT * 16) / 256, 256>>>();

    gemm1_kernel<<<dim3((NN + 31) / 32, G), 128>>>(W1, b1);
    gemm2_kernel<<<dim3((NN + 31) / 32, G), 128>>>(W2);

    gather2_kernel<<<(NTOT * 16) / 256, 256>>>(b2, out);
}

// round 4
// speedup vs baseline: 2.2443x; 1.4517x over previous
#include <cuda_runtime.h>
#include <cstdint>

#define G 4
#define NN 50000
#define EE 800000
#define F_IN 64
#define HID 128
#define OUT 64
#define NTOT (G * NN)
#define SCAN_BS 1024
#define SCAN_NB ((NTOT + SCAN_BS - 1) / SCAN_BS)   // 196

// ---- scratch ----
__device__ int   d_deg   [NTOT];
__device__ int   d_scan  [NTOT];
__device__ int   d_start [NTOT];
__device__ int   d_cursor[NTOT];
__device__ int   d_bsum  [SCAN_NB];
__device__ int   d_boff  [SCAN_NB];
__device__ int   d_csr   [(size_t)G * EE];
__device__ float d_dinv  [NTOT];
__device__ float d_xp    [(size_t)NTOT * F_IN];   // x * dinv
__device__ float d_agg   [(size_t)NTOT * F_IN];   // dinv*(sum + self)
__device__ float d_H1    [(size_t)NTOT * HID];    // elu(agg@W1+b1)
__device__ float d_h2    [(size_t)NTOT * OUT];    // (H1@W2)*dinv

__device__ __forceinline__ float elu1(float v) {
    return v > 0.f ? v : expm1f(v);
}

__device__ __forceinline__ uint32_t smem_u32(const void* p) {
    uint32_t a;
    asm("{ .reg .u64 t; cvta.to.shared.u64 t, %1; cvt.u32.u64 %0, t; }" : "=r"(a) : "l"(p));
    return a;
}

// convert 4 f32 -> tf32 and store to shared (16B aligned)
__device__ __forceinline__ void sts_tf32v4(uint32_t addr, float4 v) {
    uint32_t a, b, c, d;
    asm("cvt.rna.tf32.f32 %0, %1;" : "=r"(a) : "f"(v.x));
    asm("cvt.rna.tf32.f32 %0, %1;" : "=r"(b) : "f"(v.y));
    asm("cvt.rna.tf32.f32 %0, %1;" : "=r"(c) : "f"(v.z));
    asm("cvt.rna.tf32.f32 %0, %1;" : "=r"(d) : "f"(v.w));
    asm volatile("st.shared.v4.b32 [%0], {%1,%2,%3,%4};"
                 :: "r"(addr), "r"(a), "r"(b), "r"(c), "r"(d) : "memory");
}

// m16n8k8 tf32 MMA, C += A*B
__device__ __forceinline__ void mma8(float* c, uint32_t a0, uint32_t a1, uint32_t a2,
                                     uint32_t a3, uint32_t b0, uint32_t b1) {
    asm volatile("mma.sync.aligned.m16n8k8.row.col.f32.tf32.tf32.f32 "
                 "{%0,%1,%2,%3}, {%4,%5,%6,%7}, {%8,%9}, {%0,%1,%2,%3};"
                 : "+f"(c[0]), "+f"(c[1]), "+f"(c[2]), "+f"(c[3])
                 : "r"(a0), "r"(a1), "r"(a2), "r"(a3), "r"(b0), "r"(b1));
}

// ---------------- setup kernels ----------------
__global__ void zero_deg_kernel() {
    int i = blockIdx.x * blockDim.x + threadIdx.x;
    if (i < NTOT) d_deg[i] = 0;
}

__global__ void degree_kernel(const int* __restrict__ ei) {
    int idx = blockIdx.x * blockDim.x + threadIdx.x;
    if (idx >= G * EE) return;
    int g = idx / EE;
    int e = idx - g * EE;
    int dst = ei[(size_t)g * 2 * EE + EE + e];
    atomicAdd(&d_deg[g * NN + dst], 1);
}

__global__ void dinv_kernel() {
    int i = blockIdx.x * blockDim.x + threadIdx.x;
    if (i >= NTOT) return;
    d_dinv[i] = rsqrtf((float)(d_deg[i] + 1));
}

__global__ __launch_bounds__(256) void scan1_kernel() {
    __shared__ int sh[256];
    int b = blockIdx.x, t = threadIdx.x;
    int base = b * SCAN_BS + t * 4;
    int v[4]; int s = 0;
#pragma unroll
    for (int k = 0; k < 4; k++) {
        int i = base + k;
        v[k] = (i < NTOT) ? d_deg[i] : 0;
        s += v[k];
    }
    sh[t] = s;
    __syncthreads();
    for (int off = 1; off < 256; off <<= 1) {
        int add = (t >= off) ? sh[t - off] : 0;
        __syncthreads();
        sh[t] += add;
        __syncthreads();
    }
    int run = sh[t] - s;
#pragma unroll
    for (int k = 0; k < 4; k++) {
        run += v[k];
        if (base + k < NTOT) d_scan[base + k] = run;
    }
    if (t == 255) d_bsum[b] = sh[255];
}

__global__ __launch_bounds__(256) void scan2_kernel() {
    __shared__ int sh[256];
    int t = threadIdx.x;
    int v = (t < SCAN_NB) ? d_bsum[t] : 0;
    sh[t] = v;
    __syncthreads();
    for (int off = 1; off < 256; off <<= 1) {
        int add = (t >= off) ? sh[t - off] : 0;
        __syncthreads();
        sh[t] += add;
        __syncthreads();
    }
    if (t < SCAN_NB) d_boff[t] = sh[t] - v;
}

__global__ void scan3_kernel() {
    int i = blockIdx.x * blockDim.x + threadIdx.x;
    if (i >= NTOT) return;
    int excl = d_scan[i] - d_deg[i] + d_boff[i / SCAN_BS];
    d_start[i]  = excl;
    d_cursor[i] = excl;
}

__global__ void fill_kernel(const int* __restrict__ ei) {
    int idx = blockIdx.x * blockDim.x + threadIdx.x;
    if (idx >= G * EE) return;
    int g = idx / EE;
    int e = idx - g * EE;
    int src = ei[(size_t)g * 2 * EE + e];
    int dst = ei[(size_t)g * 2 * EE + EE + e];
    int slot = atomicAdd(&d_cursor[g * NN + dst], 1);
    d_csr[slot] = src;
}

__global__ void scale_x_kernel(const float* __restrict__ x) {
    int idx = blockIdx.x * blockDim.x + threadIdx.x;
    int row = idx >> 4;
    float4 v = ((const float4*)x)[idx];
    float dv = d_dinv[row];
    v.x *= dv; v.y *= dv; v.z *= dv; v.w *= dv;
    ((float4*)d_xp)[idx] = v;
}

// ---------------- gather layer1 ----------------
__global__ __launch_bounds__(256) void gather1_kernel() {
    int tid = blockIdx.x * 256 + threadIdx.x;
    int i = tid >> 4;
    int lane = tid & 15;
    int g = i / NN;
    int start = d_start[i];
    int d = d_deg[i];
    const float4* xv = (const float4*)d_xp;
    float4 acc = xv[(size_t)i * 16 + lane];
    int rowbase = g * NN;
    for (int c = 0; c < d; c += 16) {
        int mi = c + lane;
        int ms = (mi < d) ? d_csr[start + mi] : 0;
        int cnt = min(16, d - c);
        for (int j = 0; j < cnt; j++) {
            int src = __shfl_sync(0xffffffffu, ms, j, 16);
            float4 v = xv[(size_t)(rowbase + src) * 16 + lane];
            acc.x += v.x; acc.y += v.y; acc.z += v.z; acc.w += v.w;
        }
    }
    float dv = d_dinv[i];
    acc.x *= dv; acc.y *= dv; acc.z *= dv; acc.w *= dv;
    ((float4*)d_agg)[(size_t)i * 16 + lane] = acc;
}

// =========================================================================
// gemm1 (mma.sync tf32): H1 = elu(agg @ W1 + b1)
// CTA = 256 thr (8 warps), 128 rows/CTA; warp w -> rows [w*16, w*16+16), all 128 cols
// smem: A[128][68] tf32 @0 (34816B), B=W1^T-ish [64][136] @34816 (34816B), bias @69632
// =========================================================================
#define G1A_STRIDE 68
#define G1B_STRIDE 136
#define G1_SMEM (34816 + 34816 + 512)

__global__ __launch_bounds__(256) void gemm1_mma_kernel(const float* __restrict__ W1,
                                                        const float* __restrict__ b1) {
    extern __shared__ uint32_t smemU[];
    const uint32_t sb = smem_u32(smemU);
    uint32_t* As = smemU;                     // [row][k] stride 68
    uint32_t* Bs = smemU + 34816 / 4;         // [k][n]   stride 136
    float*    bs = (float*)(smemU + 69632 / 4);

    const int g = blockIdx.y;
    const int base = blockIdx.x * 128;
    const int t = threadIdx.x;
    const int w = t >> 5, lane = t & 31;
    const int gr = lane >> 2, q = lane & 3;

    if (t < HID) bs[t] = b1[g * HID + t];

    // A fill: 128 rows x 16 float4
    {
        const float4* Ag = (const float4*)(d_agg + ((size_t)g * NN + base) * F_IN);
        int rows = NN - base; if (rows > 128) rows = 128;
        float4 z = make_float4(0.f, 0.f, 0.f, 0.f);
        for (int i = t; i < 2048; i += 256) {
            int row = i >> 4, c4 = i & 15;
            float4 v = (row < rows) ? Ag[row * 16 + c4] : z;
            sts_tf32v4(sb + (row * G1A_STRIDE + c4 * 4) * 4, v);
        }
    }
    // B fill: W1 [64][128] -> Bs[k][n] stride 136
    {
        const float4* Wg = (const float4*)(W1 + (size_t)g * F_IN * HID);
        for (int i = t; i < 2048; i += 256) {
            int k = i >> 5, n4 = i & 31;
            float4 v = Wg[k * 32 + n4];
            sts_tf32v4(sb + 34816 + (k * G1B_STRIDE + n4 * 4) * 4, v);
        }
    }
    __syncthreads();

    float c[16][4];
#pragma unroll
    for (int nt = 0; nt < 16; nt++) { c[nt][0] = c[nt][1] = c[nt][2] = c[nt][3] = 0.f; }

    const int r0 = w * 16 + gr;
#pragma unroll
    for (int ks = 0; ks < 8; ks++) {
        int k0 = ks * 8;
        uint32_t a0 = As[r0 * G1A_STRIDE + k0 + q];
        uint32_t a1 = As[(r0 + 8) * G1A_STRIDE + k0 + q];
        uint32_t a2 = As[r0 * G1A_STRIDE + k0 + q + 4];
        uint32_t a3 = As[(r0 + 8) * G1A_STRIDE + k0 + q + 4];
#pragma unroll
        for (int nt = 0; nt < 16; nt++) {
            uint32_t b0 = Bs[(k0 + q) * G1B_STRIDE + nt * 8 + gr];
            uint32_t b1v = Bs[(k0 + q + 4) * G1B_STRIDE + nt * 8 + gr];
            mma8(c[nt], a0, a1, a2, a3, b0, b1v);
        }
    }

    // epilogue
    int row0 = base + r0, row1 = row0 + 8;
    float* H0 = d_H1 + ((size_t)g * NN + row0) * HID;
    float* H1p = d_H1 + ((size_t)g * NN + row1) * HID;
#pragma unroll
    for (int nt = 0; nt < 16; nt++) {
        int col = nt * 8 + 2 * q;
        float bx = bs[col], by = bs[col + 1];
        if (row0 < NN) {
            float2 o; o.x = elu1(c[nt][0] + bx); o.y = elu1(c[nt][1] + by);
            *(float2*)(H0 + col) = o;
        }
        if (row1 < NN) {
            float2 o; o.x = elu1(c[nt][2] + bx); o.y = elu1(c[nt][3] + by);
            *(float2*)(H1p + col) = o;
        }
    }
}

// =========================================================================
// gemm2 (mma.sync tf32): h2 = (H1 @ W2) * dinv
// CTA = 256 thr, 128 rows/CTA; warp w -> rows [w*16,+16), all 64 cols
// smem: A[128][132] @0 (67584B), B [128][72] @67584 (36864B)
// =========================================================================
#define G2A_STRIDE 132
#define G2B_STRIDE 72
#define G2_SMEM (67584 + 36864)

__global__ __launch_bounds__(256) void gemm2_mma_kernel(const float* __restrict__ W2) {
    extern __shared__ uint32_t smemU[];
    const uint32_t sb = smem_u32(smemU);
    uint32_t* As = smemU;                     // [row][k] stride 132
    uint32_t* Bs = smemU + 67584 / 4;         // [k][n]   stride 72

    const int g = blockIdx.y;
    const int base = blockIdx.x * 128;
    const int t = threadIdx.x;
    const int w = t >> 5, lane = t & 31;
    const int gr = lane >> 2, q = lane & 3;

    // A fill: 128 rows x 32 float4
    {
        const float4* Ag = (const float4*)(d_H1 + ((size_t)g * NN + base) * HID);
        int rows = NN - base; if (rows > 128) rows = 128;
        float4 z = make_float4(0.f, 0.f, 0.f, 0.f);
        for (int i = t; i < 4096; i += 256) {
            int row = i >> 5, c4 = i & 31;
            float4 v = (row < rows) ? Ag[row * 32 + c4] : z;
            sts_tf32v4(sb + (row * G2A_STRIDE + c4 * 4) * 4, v);
        }
    }
    // B fill: W2 [128][64] -> Bs[k][n] stride 72
    {
        const float4* Wg = (const float4*)(W2 + (size_t)g * HID * OUT);
        for (int i = t; i < 2048; i += 256) {
            int k = i >> 4, n4 = i & 15;
            float4 v = Wg[k * 16 + n4];
            sts_tf32v4(sb + 67584 + (k * G2B_STRIDE + n4 * 4) * 4, v);
        }
    }
    __syncthreads();

    float c[8][4];
#pragma unroll
    for (int nt = 0; nt < 8; nt++) { c[nt][0] = c[nt][1] = c[nt][2] = c[nt][3] = 0.f; }

    const int r0 = w * 16 + gr;
#pragma unroll
    for (int ks = 0; ks < 16; ks++) {
        int k0 = ks * 8;
        uint32_t a0 = As[r0 * G2A_STRIDE + k0 + q];
        uint32_t a1 = As[(r0 + 8) * G2A_STRIDE + k0 + q];
        uint32_t a2 = As[r0 * G2A_STRIDE + k0 + q + 4];
        uint32_t a3 = As[(r0 + 8) * G2A_STRIDE + k0 + q + 4];
#pragma unroll
        for (int nt = 0; nt < 8; nt++) {
            uint32_t b0 = Bs[(k0 + q) * G2B_STRIDE + nt * 8 + gr];
            uint32_t b1v = Bs[(k0 + q + 4) * G2B_STRIDE + nt * 8 + gr];
            mma8(c[nt], a0, a1, a2, a3, b0, b1v);
        }
    }

    int row0 = base + w * 16 + gr, row1 = row0 + 8;
    float dv0 = (row0 < NN) ? d_dinv[g * NN + row0] : 0.f;
    float dv1 = (row1 < NN) ? d_dinv[g * NN + row1] : 0.f;
    float* H0 = d_h2 + ((size_t)g * NN + row0) * OUT;
    float* H1p = d_h2 + ((size_t)g * NN + row1) * OUT;
#pragma unroll
    for (int nt = 0; nt < 8; nt++) {
        int col = nt * 8 + 2 * q;
        if (row0 < NN) {
            float2 o; o.x = c[nt][0] * dv0; o.y = c[nt][1] * dv0;
            *(float2*)(H0 + col) = o;
        }
        if (row1 < NN) {
            float2 o; o.x = c[nt][2] * dv1; o.y = c[nt][3] * dv1;
            *(float2*)(H1p + col) = o;
        }
    }
}

// ---------------- gather layer2 + epilogue ----------------
__global__ __launch_bounds__(256) void gather2_kernel(const float* __restrict__ b2,
                                                      float* __restrict__ out) {
    int tid = blockIdx.x * 256 + threadIdx.x;
    int i = tid >> 4;
    int lane = tid & 15;
    int g = i / NN;
    int start = d_start[i];
    int d = d_deg[i];
    const float4* hv = (const float4*)d_h2;
    float4 acc = hv[(size_t)i * 16 + lane];
    int rowbase = g * NN;
    for (int c = 0; c < d; c += 16) {
        int mi = c + lane;
        int ms = (mi < d) ? d_csr[start + mi] : 0;
        int cnt = min(16, d - c);
        for (int j = 0; j < cnt; j++) {
            int src = __shfl_sync(0xffffffffu, ms, j, 16);
            float4 v = hv[(size_t)(rowbase + src) * 16 + lane];
            acc.x += v.x; acc.y += v.y; acc.z += v.z; acc.w += v.w;
        }
    }
    float dv = d_dinv[i];
    float4 b = ((const float4*)(b2 + g * OUT))[lane];
    float4 r;
    r.x = elu1(fmaf(acc.x, dv, b.x));
    r.y = elu1(fmaf(acc.y, dv, b.y));
    r.z = elu1(fmaf(acc.z, dv, b.z));
    r.w = elu1(fmaf(acc.w, dv, b.w));
    ((float4*)out)[(size_t)i * 16 + lane] = r;
}

extern "C" void kernel_launch(void* const* d_in, const int* in_sizes, int n_in,
                              void* d_out, int out_size) {
    const float* x  = (const float*)d_in[0];
    const int*   ei = (const int*)  d_in[1];
    const float* W1 = (const float*)d_in[2];
    const float* b1 = (const float*)d_in[3];
    const float* W2 = (const float*)d_in[4];
    const float* b2 = (const float*)d_in[5];
    float* out = (float*)d_out;

    cudaFuncSetAttribute(gemm1_mma_kernel, cudaFuncAttributeMaxDynamicSharedMemorySize, G1_SMEM);
    cudaFuncSetAttribute(gemm2_mma_kernel, cudaFuncAttributeMaxDynamicSharedMemorySize, G2_SMEM);

    zero_deg_kernel<<<(NTOT + 255) / 256, 256>>>();
    degree_kernel<<<(G * EE + 255) / 256, 256>>>(ei);
    dinv_kernel<<<(NTOT + 255) / 256, 256>>>();

    scan1_kernel<<<SCAN_NB, 256>>>();
    scan2_kernel<<<1, 256>>>();
    scan3_kernel<<<(NTOT + 255) / 256, 256>>>();
    fill_kernel<<<(G * EE + 255) / 256, 256>>>(ei);

    scale_x_kernel<<<(NTOT * 16) / 256, 256>>>(x);
    gather1_kernel<<<(NTOT * 16) / 256, 256>>>();

    gemm1_mma_kernel<<<dim3((NN + 127) / 128, G), 256, G1_SMEM>>>(W1, b1);
    gemm2_mma_kernel<<<dim3((NN + 127) / 128, G), 256, G2_SMEM>>>(W2);

    gather2_kernel<<<(NTOT * 16) / 256, 256>>>(b2, out);
}

// round 5
// speedup vs baseline: 2.9238x; 1.3028x over previous
#include <cuda_runtime.h>
#include <cstdint>

#define G 4
#define NN 50000
#define EE 800000
#define F_IN 64
#define HID 128
#define OUT 64
#define NTOT (G * NN)
#define SCAN_BS 1024
#define SCAN_NB ((NTOT + SCAN_BS - 1) / SCAN_BS)   // 196

// ---- scratch ----
__device__ int   d_deg   [NTOT];
__device__ int   d_scan  [NTOT];
__device__ int   d_start [NTOT];
__device__ int   d_cursor[NTOT];
__device__ int   d_bsum  [SCAN_NB];
__device__ int   d_boff  [SCAN_NB];
__device__ int   d_csr   [(size_t)G * EE];
__device__ float d_dinv  [NTOT];
__device__ float d_agg   [(size_t)NTOT * F_IN];   // dinv*(sum dinv[s]x[s] + dinv[i]x[i])
__device__ float d_H1    [(size_t)NTOT * HID];    // elu(agg@W1+b1)
__device__ float d_h2    [(size_t)NTOT * OUT];    // (H1@W2)*dinv

__device__ __forceinline__ float elu1(float v) {
    return v > 0.f ? v : expm1f(v);
}

__device__ __forceinline__ uint32_t smem_u32(const void* p) {
    uint32_t a;
    asm("{ .reg .u64 t; cvta.to.shared.u64 t, %1; cvt.u32.u64 %0, t; }" : "=r"(a) : "l"(p));
    return a;
}

// convert 4 f32 -> tf32 and store to shared (16B aligned)
__device__ __forceinline__ void sts_tf32v4(uint32_t addr, float4 v) {
    uint32_t a, b, c, d;
    asm("cvt.rna.tf32.f32 %0, %1;" : "=r"(a) : "f"(v.x));
    asm("cvt.rna.tf32.f32 %0, %1;" : "=r"(b) : "f"(v.y));
    asm("cvt.rna.tf32.f32 %0, %1;" : "=r"(c) : "f"(v.z));
    asm("cvt.rna.tf32.f32 %0, %1;" : "=r"(d) : "f"(v.w));
    asm volatile("st.shared.v4.b32 [%0], {%1,%2,%3,%4};"
                 :: "r"(addr), "r"(a), "r"(b), "r"(c), "r"(d) : "memory");
}

// m16n8k8 tf32 MMA, C += A*B
__device__ __forceinline__ void mma8(float* c, uint32_t a0, uint32_t a1, uint32_t a2,
                                     uint32_t a3, uint32_t b0, uint32_t b1) {
    asm volatile("mma.sync.aligned.m16n8k8.row.col.f32.tf32.tf32.f32 "
                 "{%0,%1,%2,%3}, {%4,%5,%6,%7}, {%8,%9}, {%0,%1,%2,%3};"
                 : "+f"(c[0]), "+f"(c[1]), "+f"(c[2]), "+f"(c[3])
                 : "r"(a0), "r"(a1), "r"(a2), "r"(a3), "r"(b0), "r"(b1));
}

// ---------------- setup kernels ----------------
__global__ void zero_deg_kernel() {
    int i = blockIdx.x * blockDim.x + threadIdx.x;
    if (i < NTOT) d_deg[i] = 0;
}

__global__ void degree_kernel(const int* __restrict__ ei) {
    int idx = blockIdx.x * blockDim.x + threadIdx.x;
    if (idx >= G * EE) return;
    int g = idx / EE;
    int e = idx - g * EE;
    int dst = ei[(size_t)g * 2 * EE + EE + e];
    atomicAdd(&d_deg[g * NN + dst], 1);
}

__global__ void dinv_kernel() {
    int i = blockIdx.x * blockDim.x + threadIdx.x;
    if (i >= NTOT) return;
    d_dinv[i] = rsqrtf((float)(d_deg[i] + 1));
}

__global__ __launch_bounds__(256) void scan1_kernel() {
    __shared__ int sh[256];
    int b = blockIdx.x, t = threadIdx.x;
    int base = b * SCAN_BS + t * 4;
    int v[4]; int s = 0;
#pragma unroll
    for (int k = 0; k < 4; k++) {
        int i = base + k;
        v[k] = (i < NTOT) ? d_deg[i] : 0;
        s += v[k];
    }
    sh[t] = s;
    __syncthreads();
    for (int off = 1; off < 256; off <<= 1) {
        int add = (t >= off) ? sh[t - off] : 0;
        __syncthreads();
        sh[t] += add;
        __syncthreads();
    }
    int run = sh[t] - s;
#pragma unroll
    for (int k = 0; k < 4; k++) {
        run += v[k];
        if (base + k < NTOT) d_scan[base + k] = run;
    }
    if (t == 255) d_bsum[b] = sh[255];
}

__global__ __launch_bounds__(256) void scan2_kernel() {
    __shared__ int sh[256];
    int t = threadIdx.x;
    int v = (t < SCAN_NB) ? d_bsum[t] : 0;
    sh[t] = v;
    __syncthreads();
    for (int off = 1; off < 256; off <<= 1) {
        int add = (t >= off) ? sh[t - off] : 0;
        __syncthreads();
        sh[t] += add;
        __syncthreads();
    }
    if (t < SCAN_NB) d_boff[t] = sh[t] - v;
}

__global__ void scan3_kernel() {
    int i = blockIdx.x * blockDim.x + threadIdx.x;
    if (i >= NTOT) return;
    int excl = d_scan[i] - d_deg[i] + d_boff[i / SCAN_BS];
    d_start[i]  = excl;
    d_cursor[i] = excl;
}

__global__ void fill_kernel(const int* __restrict__ ei) {
    int idx = blockIdx.x * blockDim.x + threadIdx.x;
    if (idx >= G * EE) return;
    int g = idx / EE;
    int e = idx - g * EE;
    int src = ei[(size_t)g * 2 * EE + e];
    int dst = ei[(size_t)g * 2 * EE + EE + e];
    int slot = atomicAdd(&d_cursor[g * NN + dst], 1);
    d_csr[slot] = src;
}

// ---------------- gather layer1 (fused x*dinv scaling) ----------------
// 16 threads per node row; agg[i] = dinv[i]*( x[i]*dinv[i] + sum_s x[s]*dinv[s] )
__global__ __launch_bounds__(256) void gather1_kernel(const float* __restrict__ x) {
    int tid = blockIdx.x * 256 + threadIdx.x;
    int i = tid >> 4;
    int lane = tid & 15;
    int g = i / NN;
    int rowbase = g * NN;
    int start = d_start[i];
    int d = d_deg[i];
    const float4* xv = (const float4*)x;
    const int* cp = d_csr + start;
    float dvi = d_dinv[i];
    float4 self = xv[(size_t)i * 16 + lane];
    float4 acc;
    acc.x = self.x * dvi; acc.y = self.y * dvi;
    acc.z = self.z * dvi; acc.w = self.w * dvi;

    int c = 0;
    for (; c + 8 <= d; c += 8) {
#pragma unroll
        for (int jj = 0; jj < 8; jj++) {
            int sg = rowbase + __ldg(cp + c + jj);
            float ds = __ldg(d_dinv + sg);
            float4 v = xv[(size_t)sg * 16 + lane];
            acc.x = fmaf(v.x, ds, acc.x);
            acc.y = fmaf(v.y, ds, acc.y);
            acc.z = fmaf(v.z, ds, acc.z);
            acc.w = fmaf(v.w, ds, acc.w);
        }
    }
    for (; c < d; c++) {
        int sg = rowbase + __ldg(cp + c);
        float ds = __ldg(d_dinv + sg);
        float4 v = xv[(size_t)sg * 16 + lane];
        acc.x = fmaf(v.x, ds, acc.x);
        acc.y = fmaf(v.y, ds, acc.y);
        acc.z = fmaf(v.z, ds, acc.z);
        acc.w = fmaf(v.w, ds, acc.w);
    }
    acc.x *= dvi; acc.y *= dvi; acc.z *= dvi; acc.w *= dvi;
    ((float4*)d_agg)[(size_t)i * 16 + lane] = acc;
}

// =========================================================================
// gemm1 (mma.sync tf32): H1 = elu(agg @ W1 + b1)
// =========================================================================
#define G1A_STRIDE 68
#define G1B_STRIDE 136
#define G1_SMEM (34816 + 34816 + 512)

__global__ __launch_bounds__(256) void gemm1_mma_kernel(const float* __restrict__ W1,
                                                        const float* __restrict__ b1) {
    extern __shared__ uint32_t smemU[];
    const uint32_t sb = smem_u32(smemU);
    uint32_t* As = smemU;                     // [row][k] stride 68
    uint32_t* Bs = smemU + 34816 / 4;         // [k][n]   stride 136
    float*    bs = (float*)(smemU + 69632 / 4);

    const int g = blockIdx.y;
    const int base = blockIdx.x * 128;
    const int t = threadIdx.x;
    const int w = t >> 5, lane = t & 31;
    const int gr = lane >> 2, q = lane & 3;

    if (t < HID) bs[t] = b1[g * HID + t];

    {
        const float4* Ag = (const float4*)(d_agg + ((size_t)g * NN + base) * F_IN);
        int rows = NN - base; if (rows > 128) rows = 128;
        float4 z = make_float4(0.f, 0.f, 0.f, 0.f);
        for (int i = t; i < 2048; i += 256) {
            int row = i >> 4, c4 = i & 15;
            float4 v = (row < rows) ? Ag[row * 16 + c4] : z;
            sts_tf32v4(sb + (row * G1A_STRIDE + c4 * 4) * 4, v);
        }
    }
    {
        const float4* Wg = (const float4*)(W1 + (size_t)g * F_IN * HID);
        for (int i = t; i < 2048; i += 256) {
            int k = i >> 5, n4 = i & 31;
            float4 v = Wg[k * 32 + n4];
            sts_tf32v4(sb + 34816 + (k * G1B_STRIDE + n4 * 4) * 4, v);
        }
    }
    __syncthreads();

    float c[16][4];
#pragma unroll
    for (int nt = 0; nt < 16; nt++) { c[nt][0] = c[nt][1] = c[nt][2] = c[nt][3] = 0.f; }

    const int r0 = w * 16 + gr;
#pragma unroll
    for (int ks = 0; ks < 8; ks++) {
        int k0 = ks * 8;
        uint32_t a0 = As[r0 * G1A_STRIDE + k0 + q];
        uint32_t a1 = As[(r0 + 8) * G1A_STRIDE + k0 + q];
        uint32_t a2 = As[r0 * G1A_STRIDE + k0 + q + 4];
        uint32_t a3 = As[(r0 + 8) * G1A_STRIDE + k0 + q + 4];
#pragma unroll
        for (int nt = 0; nt < 16; nt++) {
            uint32_t b0 = Bs[(k0 + q) * G1B_STRIDE + nt * 8 + gr];
            uint32_t b1v = Bs[(k0 + q + 4) * G1B_STRIDE + nt * 8 + gr];
            mma8(c[nt], a0, a1, a2, a3, b0, b1v);
        }
    }

    int row0 = base + r0, row1 = row0 + 8;
    float* H0 = d_H1 + ((size_t)g * NN + row0) * HID;
    float* H1p = d_H1 + ((size_t)g * NN + row1) * HID;
#pragma unroll
    for (int nt = 0; nt < 16; nt++) {
        int col = nt * 8 + 2 * q;
        float bx = bs[col], by = bs[col + 1];
        if (row0 < NN) {
            float2 o; o.x = elu1(c[nt][0] + bx); o.y = elu1(c[nt][1] + by);
            *(float2*)(H0 + col) = o;
        }
        if (row1 < NN) {
            float2 o; o.x = elu1(c[nt][2] + bx); o.y = elu1(c[nt][3] + by);
            *(float2*)(H1p + col) = o;
        }
    }
}

// =========================================================================
// gemm2 (mma.sync tf32): h2 = (H1 @ W2) * dinv
// =========================================================================
#define G2A_STRIDE 132
#define G2B_STRIDE 72
#define G2_SMEM (67584 + 36864)

__global__ __launch_bounds__(256) void gemm2_mma_kernel(const float* __restrict__ W2) {
    extern __shared__ uint32_t smemU[];
    const uint32_t sb = smem_u32(smemU);
    uint32_t* As = smemU;                     // [row][k] stride 132
    uint32_t* Bs = smemU + 67584 / 4;         // [k][n]   stride 72

    const int g = blockIdx.y;
    const int base = blockIdx.x * 128;
    const int t = threadIdx.x;
    const int w = t >> 5, lane = t & 31;
    const int gr = lane >> 2, q = lane & 3;

    {
        const float4* Ag = (const float4*)(d_H1 + ((size_t)g * NN + base) * HID);
        int rows = NN - base; if (rows > 128) rows = 128;
        float4 z = make_float4(0.f, 0.f, 0.f, 0.f);
        for (int i = t; i < 4096; i += 256) {
            int row = i >> 5, c4 = i & 31;
            float4 v = (row < rows) ? Ag[row * 32 + c4] : z;
            sts_tf32v4(sb + (row * G2A_STRIDE + c4 * 4) * 4, v);
        }
    }
    {
        const float4* Wg = (const float4*)(W2 + (size_t)g * HID * OUT);
        for (int i = t; i < 2048; i += 256) {
            int k = i >> 4, n4 = i & 15;
            float4 v = Wg[k * 16 + n4];
            sts_tf32v4(sb + 67584 + (k * G2B_STRIDE + n4 * 4) * 4, v);
        }
    }
    __syncthreads();

    float c[8][4];
#pragma unroll
    for (int nt = 0; nt < 8; nt++) { c[nt][0] = c[nt][1] = c[nt][2] = c[nt][3] = 0.f; }

    const int r0 = w * 16 + gr;
#pragma unroll
    for (int ks = 0; ks < 16; ks++) {
        int k0 = ks * 8;
        uint32_t a0 = As[r0 * G2A_STRIDE + k0 + q];
        uint32_t a1 = As[(r0 + 8) * G2A_STRIDE + k0 + q];
        uint32_t a2 = As[r0 * G2A_STRIDE + k0 + q + 4];
        uint32_t a3 = As[(r0 + 8) * G2A_STRIDE + k0 + q + 4];
#pragma unroll
        for (int nt = 0; nt < 8; nt++) {
            uint32_t b0 = Bs[(k0 + q) * G2B_STRIDE + nt * 8 + gr];
            uint32_t b1v = Bs[(k0 + q + 4) * G2B_STRIDE + nt * 8 + gr];
            mma8(c[nt], a0, a1, a2, a3, b0, b1v);
        }
    }

    int row0 = base + w * 16 + gr, row1 = row0 + 8;
    float dv0 = (row0 < NN) ? d_dinv[g * NN + row0] : 0.f;
    float dv1 = (row1 < NN) ? d_dinv[g * NN + row1] : 0.f;
    float* H0 = d_h2 + ((size_t)g * NN + row0) * OUT;
    float* H1p = d_h2 + ((size_t)g * NN + row1) * OUT;
#pragma unroll
    for (int nt = 0; nt < 8; nt++) {
        int col = nt * 8 + 2 * q;
        if (row0 < NN) {
            float2 o; o.x = c[nt][0] * dv0; o.y = c[nt][1] * dv0;
            *(float2*)(H0 + col) = o;
        }
        if (row1 < NN) {
            float2 o; o.x = c[nt][2] * dv1; o.y = c[nt][3] * dv1;
            *(float2*)(H1p + col) = o;
        }
    }
}

// ---------------- gather layer2 + epilogue ----------------
__global__ __launch_bounds__(256) void gather2_kernel(const float* __restrict__ b2,
                                                      float* __restrict__ out) {
    int tid = blockIdx.x * 256 + threadIdx.x;
    int i = tid >> 4;
    int lane = tid & 15;
    int g = i / NN;
    int rowbase = g * NN;
    int start = d_start[i];
    int d = d_deg[i];
    const float4* hv = (const float4*)d_h2;
    const int* cp = d_csr + start;
    float4 acc = hv[(size_t)i * 16 + lane];   // self loop (pre-scaled)

    int c = 0;
    for (; c + 8 <= d; c += 8) {
#pragma unroll
        for (int jj = 0; jj < 8; jj++) {
            int sg = rowbase + __ldg(cp + c + jj);
            float4 v = hv[(size_t)sg * 16 + lane];
            acc.x += v.x; acc.y += v.y; acc.z += v.z; acc.w += v.w;
        }
    }
    for (; c < d; c++) {
        int sg = rowbase + __ldg(cp + c);
        float4 v = hv[(size_t)sg * 16 + lane];
        acc.x += v.x; acc.y += v.y; acc.z += v.z; acc.w += v.w;
    }

    float dv = d_dinv[i];
    float4 b = ((const float4*)(b2 + g * OUT))[lane];
    float4 r;
    r.x = elu1(fmaf(acc.x, dv, b.x));
    r.y = elu1(fmaf(acc.y, dv, b.y));
    r.z = elu1(fmaf(acc.z, dv, b.z));
    r.w = elu1(fmaf(acc.w, dv, b.w));
    ((float4*)out)[(size_t)i * 16 + lane] = r;
}

extern "C" void kernel_launch(void* const* d_in, const int* in_sizes, int n_in,
                              void* d_out, int out_size) {
    const float* x  = (const float*)d_in[0];
    const int*   ei = (const int*)  d_in[1];
    const float* W1 = (const float*)d_in[2];
    const float* b1 = (const float*)d_in[3];
    const float* W2 = (const float*)d_in[4];
    const float* b2 = (const float*)d_in[5];
    float* out = (float*)d_out;

    cudaFuncSetAttribute(gemm1_mma_kernel, cudaFuncAttributeMaxDynamicSharedMemorySize, G1_SMEM);
    cudaFuncSetAttribute(gemm2_mma_kernel, cudaFuncAttributeMaxDynamicSharedMemorySize, G2_SMEM);

    zero_deg_kernel<<<(NTOT + 255) / 256, 256>>>();
    degree_kernel<<<(G * EE + 255) / 256, 256>>>(ei);
    dinv_kernel<<<(NTOT + 255) / 256, 256>>>();

    scan1_kernel<<<SCAN_NB, 256>>>();
    scan2_kernel<<<1, 256>>>();
    scan3_kernel<<<(NTOT + 255) / 256, 256>>>();
    fill_kernel<<<(G * EE + 255) / 256, 256>>>(ei);

    gather1_kernel<<<(NTOT * 16) / 256, 256>>>(x);

    gemm1_mma_kernel<<<dim3((NN + 127) / 128, G), 256, G1_SMEM>>>(W1, b1);
    gemm2_mma_kernel<<<dim3((NN + 127) / 128, G), 256, G2_SMEM>>>(W2);

    gather2_kernel<<<(NTOT * 16) / 256, 256>>>(b2, out);
}

// round 6
// speedup vs baseline: 3.2794x; 1.1216x over previous
#include <cuda_runtime.h>
#include <cstdint>

#define G 4
#define NN 50000
#define EE 800000
#define F_IN 64
#define HID 128
#define OUT 64
#define NTOT (G * NN)
#define SCAN_BS 1024
#define SCAN_NB ((NTOT + SCAN_BS - 1) / SCAN_BS)   // 196

// ---- scratch ----
__device__ int   d_deg   [NTOT];
__device__ int   d_scan  [NTOT];
__device__ int   d_start [NTOT];
__device__ int   d_cursor[NTOT];
__device__ int   d_bsum  [SCAN_NB];
__device__ int   d_boff  [SCAN_NB];
__device__ int   d_csr   [(size_t)G * EE];
__device__ float d_dinv  [NTOT];
__device__ float d_agg   [(size_t)NTOT * F_IN];   // dinv*(sum dinv[s]x[s] + dinv[i]x[i])
__device__ float d_h2    [(size_t)NTOT * OUT];    // (elu(agg@W1+b1)@W2)*dinv

__device__ __forceinline__ float elu1(float v) {
    return v > 0.f ? v : expm1f(v);
}

__device__ __forceinline__ uint32_t smem_u32(const void* p) {
    uint32_t a;
    asm("{ .reg .u64 t; cvta.to.shared.u64 t, %1; cvt.u32.u64 %0, t; }" : "=r"(a) : "l"(p));
    return a;
}

__device__ __forceinline__ void sts_tf32v4(uint32_t addr, float4 v) {
    uint32_t a, b, c, d;
    asm("cvt.rna.tf32.f32 %0, %1;" : "=r"(a) : "f"(v.x));
    asm("cvt.rna.tf32.f32 %0, %1;" : "=r"(b) : "f"(v.y));
    asm("cvt.rna.tf32.f32 %0, %1;" : "=r"(c) : "f"(v.z));
    asm("cvt.rna.tf32.f32 %0, %1;" : "=r"(d) : "f"(v.w));
    asm volatile("st.shared.v4.b32 [%0], {%1,%2,%3,%4};"
                 :: "r"(addr), "r"(a), "r"(b), "r"(c), "r"(d) : "memory");
}

__device__ __forceinline__ void sts_tf32v2(uint32_t addr, float x, float y) {
    uint32_t a, b;
    asm("cvt.rna.tf32.f32 %0, %1;" : "=r"(a) : "f"(x));
    asm("cvt.rna.tf32.f32 %0, %1;" : "=r"(b) : "f"(y));
    asm volatile("st.shared.v2.b32 [%0], {%1,%2};"
                 :: "r"(addr), "r"(a), "r"(b) : "memory");
}

// m16n8k8 tf32 MMA, C += A*B
__device__ __forceinline__ void mma8(float* c, uint32_t a0, uint32_t a1, uint32_t a2,
                                     uint32_t a3, uint32_t b0, uint32_t b1) {
    asm volatile("mma.sync.aligned.m16n8k8.row.col.f32.tf32.tf32.f32 "
                 "{%0,%1,%2,%3}, {%4,%5,%6,%7}, {%8,%9}, {%0,%1,%2,%3};"
                 : "+f"(c[0]), "+f"(c[1]), "+f"(c[2]), "+f"(c[3])
                 : "r"(a0), "r"(a1), "r"(a2), "r"(a3), "r"(b0), "r"(b1));
}

// ---------------- setup kernels ----------------
__global__ void zero_deg_kernel() {
    int i = blockIdx.x * blockDim.x + threadIdx.x;
    if (i < NTOT) d_deg[i] = 0;
}

__global__ void degree_kernel(const int* __restrict__ ei) {
    int idx = blockIdx.x * blockDim.x + threadIdx.x;
    if (idx >= G * EE) return;
    int g = idx / EE;
    int e = idx - g * EE;
    int dst = ei[(size_t)g * 2 * EE + EE + e];
    atomicAdd(&d_deg[g * NN + dst], 1);
}

__global__ __launch_bounds__(256) void scan1_kernel() {
    __shared__ int sh[256];
    int b = blockIdx.x, t = threadIdx.x;
    int base = b * SCAN_BS + t * 4;
    int v[4]; int s = 0;
#pragma unroll
    for (int k = 0; k < 4; k++) {
        int i = base + k;
        v[k] = (i < NTOT) ? d_deg[i] : 0;
        s += v[k];
    }
    sh[t] = s;
    __syncthreads();
    for (int off = 1; off < 256; off <<= 1) {
        int add = (t >= off) ? sh[t - off] : 0;
        __syncthreads();
        sh[t] += add;
        __syncthreads();
    }
    int run = sh[t] - s;
#pragma unroll
    for (int k = 0; k < 4; k++) {
        run += v[k];
        if (base + k < NTOT) d_scan[base + k] = run;
    }
    if (t == 255) d_bsum[b] = sh[255];
}

__global__ __launch_bounds__(256) void scan2_kernel() {
    __shared__ int sh[256];
    int t = threadIdx.x;
    int v = (t < SCAN_NB) ? d_bsum[t] : 0;
    sh[t] = v;
    __syncthreads();
    for (int off = 1; off < 256; off <<= 1) {
        int add = (t >= off) ? sh[t - off] : 0;
        __syncthreads();
        sh[t] += add;
        __syncthreads();
    }
    if (t < SCAN_NB) d_boff[t] = sh[t] - v;
}

// scan3 + dinv fused
__global__ void scan3_kernel() {
    int i = blockIdx.x * blockDim.x + threadIdx.x;
    if (i >= NTOT) return;
    int dg = d_deg[i];
    int excl = d_scan[i] - dg + d_boff[i / SCAN_BS];
    d_start[i]  = excl;
    d_cursor[i] = excl;
    d_dinv[i] = rsqrtf((float)(dg + 1));
}

__global__ void fill_kernel(const int* __restrict__ ei) {
    int idx = blockIdx.x * blockDim.x + threadIdx.x;
    if (idx >= G * EE) return;
    int g = idx / EE;
    int e = idx - g * EE;
    int src = ei[(size_t)g * 2 * EE + e];
    int dst = ei[(size_t)g * 2 * EE + EE + e];
    int slot = atomicAdd(&d_cursor[g * NN + dst], 1);
    d_csr[slot] = src;
}

// ---------------- gather layer1 (fused x*dinv scaling) ----------------
__global__ __launch_bounds__(256) void gather1_kernel(const float* __restrict__ x) {
    int tid = blockIdx.x * 256 + threadIdx.x;
    int i = tid >> 4;
    int lane = tid & 15;
    int g = i / NN;
    int rowbase = g * NN;
    int start = d_start[i];
    int d = d_deg[i];
    const float4* xv = (const float4*)x;
    const int* cp = d_csr + start;
    float dvi = d_dinv[i];
    float4 self = xv[(size_t)i * 16 + lane];
    float4 acc;
    acc.x = self.x * dvi; acc.y = self.y * dvi;
    acc.z = self.z * dvi; acc.w = self.w * dvi;

    int c = 0;
    for (; c + 8 <= d; c += 8) {
#pragma unroll
        for (int jj = 0; jj < 8; jj++) {
            int sg = rowbase + __ldg(cp + c + jj);
            float ds = __ldg(d_dinv + sg);
            float4 v = xv[(size_t)sg * 16 + lane];
            acc.x = fmaf(v.x, ds, acc.x);
            acc.y = fmaf(v.y, ds, acc.y);
            acc.z = fmaf(v.z, ds, acc.z);
            acc.w = fmaf(v.w, ds, acc.w);
        }
    }
    for (; c < d; c++) {
        int sg = rowbase + __ldg(cp + c);
        float ds = __ldg(d_dinv + sg);
        float4 v = xv[(size_t)sg * 16 + lane];
        acc.x = fmaf(v.x, ds, acc.x);
        acc.y = fmaf(v.y, ds, acc.y);
        acc.z = fmaf(v.z, ds, acc.z);
        acc.w = fmaf(v.w, ds, acc.w);
    }
    acc.x *= dvi; acc.y *= dvi; acc.z *= dvi; acc.w *= dvi;
    ((float4*)d_agg)[(size_t)i * 16 + lane] = acc;
}

// =========================================================================
// fused gemm (mma.sync tf32): h2 = elu(agg@W1+b1) @ W2 * dinv, H1 stays in SMEM
// smem layout (bytes):
//   [0, 34816)        As   : agg tile  [128][68]  tf32    (phase 1)
//   [34816, 69632)    Bs1  : W1        [64][136]  tf32    (phase 1)
//   [0, 67584)        A2   : H1 tile   [128][132] tf32    (phase 2, aliases As/Bs1)
//   [69632, 106496)   Bs2  : W2        [128][72]  tf32
//   [106496, 107008)  bias1
// =========================================================================
#define FA_STRIDE 68
#define FB1_STRIDE 136
#define FA2_STRIDE 132
#define FB2_STRIDE 72
#define FB2_OFF 69632
#define FBIAS_OFF 106496
#define FUSED_SMEM 107008

__global__ __launch_bounds__(256) void fused_gemm_kernel(const float* __restrict__ W1,
                                                         const float* __restrict__ b1,
                                                         const float* __restrict__ W2) {
    extern __shared__ uint32_t smemU[];
    const uint32_t sb = smem_u32(smemU);
    uint32_t* As  = smemU;                       // stride 68 (phase 1)
    uint32_t* Bs1 = smemU + 34816 / 4;           // stride 136
    uint32_t* A2  = smemU;                       // stride 132 (phase 2)
    uint32_t* Bs2 = smemU + FB2_OFF / 4;         // stride 72
    float*    bs  = (float*)(smemU + FBIAS_OFF / 4);

    const int g = blockIdx.y;
    const int base = blockIdx.x * 128;
    const int t = threadIdx.x;
    const int w = t >> 5, lane = t & 31;
    const int gr = lane >> 2, q = lane & 3;

    if (t < HID) bs[t] = b1[g * HID + t];

    // As fill: agg tile 128 x 64
    {
        const float4* Ag = (const float4*)(d_agg + ((size_t)g * NN + base) * F_IN);
        int rows = NN - base; if (rows > 128) rows = 128;
        float4 z = make_float4(0.f, 0.f, 0.f, 0.f);
        for (int i = t; i < 2048; i += 256) {
            int row = i >> 4, c4 = i & 15;
            float4 v = (row < rows) ? Ag[row * 16 + c4] : z;
            sts_tf32v4(sb + (row * FA_STRIDE + c4 * 4) * 4, v);
        }
    }
    // Bs1 fill: W1 [64][128]
    {
        const float4* Wg = (const float4*)(W1 + (size_t)g * F_IN * HID);
        for (int i = t; i < 2048; i += 256) {
            int k = i >> 5, n4 = i & 31;
            float4 v = Wg[k * 32 + n4];
            sts_tf32v4(sb + 34816 + (k * FB1_STRIDE + n4 * 4) * 4, v);
        }
    }
    // Bs2 fill: W2 [128][64]
    {
        const float4* Wg = (const float4*)(W2 + (size_t)g * HID * OUT);
        for (int i = t; i < 2048; i += 256) {
            int k = i >> 4, n4 = i & 15;
            float4 v = Wg[k * 16 + n4];
            sts_tf32v4(sb + FB2_OFF + (k * FB2_STRIDE + n4 * 4) * 4, v);
        }
    }
    __syncthreads();

    const int r0 = w * 16 + gr;

    // ---- MMA chain 1: C1[16 rows x 128 cols per warp] ----
    float c1[16][4];
#pragma unroll
    for (int nt = 0; nt < 16; nt++) { c1[nt][0] = c1[nt][1] = c1[nt][2] = c1[nt][3] = 0.f; }
#pragma unroll
    for (int ks = 0; ks < 8; ks++) {
        int k0 = ks * 8;
        uint32_t a0 = As[r0 * FA_STRIDE + k0 + q];
        uint32_t a1 = As[(r0 + 8) * FA_STRIDE + k0 + q];
        uint32_t a2 = As[r0 * FA_STRIDE + k0 + q + 4];
        uint32_t a3 = As[(r0 + 8) * FA_STRIDE + k0 + q + 4];
#pragma unroll
        for (int nt = 0; nt < 16; nt++) {
            uint32_t b0 = Bs1[(k0 + q) * FB1_STRIDE + nt * 8 + gr];
            uint32_t b1v = Bs1[(k0 + q + 4) * FB1_STRIDE + nt * 8 + gr];
            mma8(c1[nt], a0, a1, a2, a3, b0, b1v);
        }
    }
    __syncthreads();   // all warps done reading As/Bs1

    // ---- epilogue 1: A2 = tf32(elu(C1 + bias)) ----
#pragma unroll
    for (int nt = 0; nt < 16; nt++) {
        int col = nt * 8 + 2 * q;
        float bx = bs[col], by = bs[col + 1];
        sts_tf32v2(sb + (r0 * FA2_STRIDE + col) * 4,
                   elu1(c1[nt][0] + bx), elu1(c1[nt][1] + by));
        sts_tf32v2(sb + ((r0 + 8) * FA2_STRIDE + col) * 4,
                   elu1(c1[nt][2] + bx), elu1(c1[nt][3] + by));
    }
    __syncthreads();

    // ---- MMA chain 2: C2[16 rows x 64 cols per warp] ----
    float c2[8][4];
#pragma unroll
    for (int nt = 0; nt < 8; nt++) { c2[nt][0] = c2[nt][1] = c2[nt][2] = c2[nt][3] = 0.f; }
#pragma unroll
    for (int ks = 0; ks < 16; ks++) {
        int k0 = ks * 8;
        uint32_t a0 = A2[r0 * FA2_STRIDE + k0 + q];
        uint32_t a1 = A2[(r0 + 8) * FA2_STRIDE + k0 + q];
        uint32_t a2 = A2[r0 * FA2_STRIDE + k0 + q + 4];
        uint32_t a3 = A2[(r0 + 8) * FA2_STRIDE + k0 + q + 4];
#pragma unroll
        for (int nt = 0; nt < 8; nt++) {
            uint32_t b0 = Bs2[(k0 + q) * FB2_STRIDE + nt * 8 + gr];
            uint32_t b1v = Bs2[(k0 + q + 4) * FB2_STRIDE + nt * 8 + gr];
            mma8(c2[nt], a0, a1, a2, a3, b0, b1v);
        }
    }

    // ---- epilogue 2: h2 = C2 * dinv ----
    int row0 = base + r0, row1 = row0 + 8;
    float dv0 = (row0 < NN) ? d_dinv[g * NN + row0] : 0.f;
    float dv1 = (row1 < NN) ? d_dinv[g * NN + row1] : 0.f;
    float* H0 = d_h2 + ((size_t)g * NN + row0) * OUT;
    float* H1p = d_h2 + ((size_t)g * NN + row1) * OUT;
#pragma unroll
    for (int nt = 0; nt < 8; nt++) {
        int col = nt * 8 + 2 * q;
        if (row0 < NN) {
            float2 o; o.x = c2[nt][0] * dv0; o.y = c2[nt][1] * dv0;
            *(float2*)(H0 + col) = o;
        }
        if (row1 < NN) {
            float2 o; o.x = c2[nt][2] * dv1; o.y = c2[nt][3] * dv1;
            *(float2*)(H1p + col) = o;
        }
    }
}

// ---------------- gather layer2 + epilogue ----------------
__global__ __launch_bounds__(256) void gather2_kernel(const float* __restrict__ b2,
                                                      float* __restrict__ out) {
    int tid = blockIdx.x * 256 + threadIdx.x;
    int i = tid >> 4;
    int lane = tid & 15;
    int g = i / NN;
    int rowbase = g * NN;
    int start = d_start[i];
    int d = d_deg[i];
    const float4* hv = (const float4*)d_h2;
    const int* cp = d_csr + start;
    float4 acc = hv[(size_t)i * 16 + lane];   // self loop (pre-scaled)

    int c = 0;
    for (; c + 8 <= d; c += 8) {
#pragma unroll
        for (int jj = 0; jj < 8; jj++) {
            int sg = rowbase + __ldg(cp + c + jj);
            float4 v = hv[(size_t)sg * 16 + lane];
            acc.x += v.x; acc.y += v.y; acc.z += v.z; acc.w += v.w;
        }
    }
    for (; c < d; c++) {
        int sg = rowbase + __ldg(cp + c);
        float4 v = hv[(size_t)sg * 16 + lane];
        acc.x += v.x; acc.y += v.y; acc.z += v.z; acc.w += v.w;
    }

    float dv = d_dinv[i];
    float4 b = ((const float4*)(b2 + g * OUT))[lane];
    float4 r;
    r.x = elu1(fmaf(acc.x, dv, b.x));
    r.y = elu1(fmaf(acc.y, dv, b.y));
    r.z = elu1(fmaf(acc.z, dv, b.z));
    r.w = elu1(fmaf(acc.w, dv, b.w));
    ((float4*)out)[(size_t)i * 16 + lane] = r;
}

extern "C" void kernel_launch(void* const* d_in, const int* in_sizes, int n_in,
                              void* d_out, int out_size) {
    const float* x  = (const float*)d_in[0];
    const int*   ei = (const int*)  d_in[1];
    const float* W1 = (const float*)d_in[2];
    const float* b1 = (const float*)d_in[3];
    const float* W2 = (const float*)d_in[4];
    const float* b2 = (const float*)d_in[5];
    float* out = (float*)d_out;

    cudaFuncSetAttribute(fused_gemm_kernel, cudaFuncAttributeMaxDynamicSharedMemorySize, FUSED_SMEM);

    zero_deg_kernel<<<(NTOT + 255) / 256, 256>>>();
    degree_kernel<<<(G * EE + 255) / 256, 256>>>(ei);

    scan1_kernel<<<SCAN_NB, 256>>>();
    scan2_kernel<<<1, 256>>>();
    scan3_kernel<<<(NTOT + 255) / 256, 256>>>();
    fill_kernel<<<(G * EE + 255) / 256, 256>>>(ei);

    gather1_kernel<<<(NTOT * 16) / 256, 256>>>(x);

    fused_gemm_kernel<<<dim3((NN + 127) / 128, G), 256, FUSED_SMEM>>>(W1, b1, W2);

    gather2_kernel<<<(NTOT * 16) / 256, 256>>>(b2, out);
}

// round 9
// speedup vs baseline: 3.4024x; 1.0375x over previous
#include <cuda_runtime.h>
#include <cuda_fp16.h>
#include <cstdint>

#define G 4
#define NN 50000
#define EE 800000
#define F_IN 64
#define HID 128
#define OUT 64
#define NTOT (G * NN)
#define SCAN_NB_G 49   // ceil(50000/1024)

// ---- scratch ----
__device__ int    d_deg   [NTOT];
__device__ int    d_scan  [NTOT];
__device__ int    d_start [NTOT];   // per-graph-relative CSR offsets
__device__ int    d_cursor[NTOT];
__device__ int    d_bsum  [G][64];
__device__ int    d_csr   [(size_t)G * EE];
__device__ float  d_dinv  [NTOT];
__device__ float  d_agg   [(size_t)NTOT * F_IN];
__device__ __half d_h2    [(size_t)NTOT * OUT];   // fp16 intermediate

__device__ __forceinline__ float elu1(float v) {
    return v > 0.f ? v : expm1f(v);
}

__device__ __forceinline__ uint32_t smem_u32(const void* p) {
    uint32_t a;
    asm("{ .reg .u64 t; cvta.to.shared.u64 t, %1; cvt.u32.u64 %0, t; }" : "=r"(a) : "l"(p));
    return a;
}

__device__ __forceinline__ void sts_tf32v4(uint32_t addr, float4 v) {
    uint32_t a, b, c, d;
    asm("cvt.rna.tf32.f32 %0, %1;" : "=r"(a) : "f"(v.x));
    asm("cvt.rna.tf32.f32 %0, %1;" : "=r"(b) : "f"(v.y));
    asm("cvt.rna.tf32.f32 %0, %1;" : "=r"(c) : "f"(v.z));
    asm("cvt.rna.tf32.f32 %0, %1;" : "=r"(d) : "f"(v.w));
    asm volatile("st.shared.v4.b32 [%0], {%1,%2,%3,%4};"
                 :: "r"(addr), "r"(a), "r"(b), "r"(c), "r"(d) : "memory");
}

__device__ __forceinline__ void sts_tf32v2(uint32_t addr, float x, float y) {
    uint32_t a, b;
    asm("cvt.rna.tf32.f32 %0, %1;" : "=r"(a) : "f"(x));
    asm("cvt.rna.tf32.f32 %0, %1;" : "=r"(b) : "f"(y));
    asm volatile("st.shared.v2.b32 [%0], {%1,%2};"
                 :: "r"(addr), "r"(a), "r"(b) : "memory");
}

__device__ __forceinline__ void mma8(float* c, uint32_t a0, uint32_t a1, uint32_t a2,
                                     uint32_t a3, uint32_t b0, uint32_t b1) {
    asm volatile("mma.sync.aligned.m16n8k8.row.col.f32.tf32.tf32.f32 "
                 "{%0,%1,%2,%3}, {%4,%5,%6,%7}, {%8,%9}, {%0,%1,%2,%3};"
                 : "+f"(c[0]), "+f"(c[1]), "+f"(c[2]), "+f"(c[3])
                 : "r"(a0), "r"(a1), "r"(a2), "r"(a3), "r"(b0), "r"(b1));
}

__device__ __forceinline__ void acc_half8(float* acc, uint4 v) {
    float2 p;
    p = __half22float2(*(__half2*)&v.x); acc[0] += p.x; acc[1] += p.y;
    p = __half22float2(*(__half2*)&v.y); acc[2] += p.x; acc[3] += p.y;
    p = __half22float2(*(__half2*)&v.z); acc[4] += p.x; acc[5] += p.y;
    p = __half22float2(*(__half2*)&v.w); acc[6] += p.x; acc[7] += p.y;
}

// ---------------- setup kernels ----------------
__global__ void zero_deg_kernel() {
    int i = blockIdx.x * blockDim.x + threadIdx.x;
    if (i < NTOT) d_deg[i] = 0;
}

__global__ void degree_kernel(const int* __restrict__ ei) {
    int idx = blockIdx.x * blockDim.x + threadIdx.x;
    if (idx >= G * EE) return;
    int g = idx / EE;
    int e = idx - g * EE;
    int dst = ei[(size_t)g * 2 * EE + EE + e];
    atomicAdd(&d_deg[g * NN + dst], 1);
}

// per-graph inclusive scan over 1024-node chunks; grid (49, G)
__global__ __launch_bounds__(256) void scan1_kernel() {
    __shared__ int sh[256];
    int g = blockIdx.y;
    int b = blockIdx.x, t = threadIdx.x;
    int lbase = b * 1024 + t * 4;
    int v[4]; int s = 0;
#pragma unroll
    for (int k = 0; k < 4; k++) {
        int li = lbase + k;
        v[k] = (li < NN) ? d_deg[g * NN + li] : 0;
        s += v[k];
    }
    sh[t] = s;
    __syncthreads();
    for (int off = 1; off < 256; off <<= 1) {
        int add = (t >= off) ? sh[t - off] : 0;
        __syncthreads();
        sh[t] += add;
        __syncthreads();
    }
    int run = sh[t] - s;
#pragma unroll
    for (int k = 0; k < 4; k++) {
        run += v[k];
        int li = lbase + k;
        if (li < NN) d_scan[g * NN + li] = run;
    }
    if (t == 255) d_bsum[g][b] = sh[255];
}

// fused scan2+scan3+dinv; grid ((NN+255)/256, G)
__global__ __launch_bounds__(256) void scan23_kernel() {
    __shared__ int bsh[64];
    __shared__ int boff_sh;
    int g = blockIdx.y;
    int t = threadIdx.x;
    int li = blockIdx.x * 256 + t;
    if (t < SCAN_NB_G) bsh[t] = d_bsum[g][t];
    __syncthreads();
    if (t == 0) {
        int blk = blockIdx.x >> 2;   // 256*4 = 1024 nodes per scan1 block
        int s = 0;
        for (int j = 0; j < blk; j++) s += bsh[j];
        boff_sh = s;
    }
    __syncthreads();
    if (li >= NN) return;
    int i = g * NN + li;
    int dg = d_deg[i];
    int excl = d_scan[i] - dg + boff_sh;
    d_start[i]  = excl;
    d_cursor[i] = excl;
    d_dinv[i] = rsqrtf((float)(dg + 1));
}

__global__ void fill_kernel(const int* __restrict__ ei) {
    int idx = blockIdx.x * blockDim.x + threadIdx.x;
    if (idx >= G * EE) return;
    int g = idx / EE;
    int e = idx - g * EE;
    int src = ei[(size_t)g * 2 * EE + e];
    int dst = ei[(size_t)g * 2 * EE + EE + e];
    int slot = atomicAdd(&d_cursor[g * NN + dst], 1);
    d_csr[(size_t)g * EE + slot] = src;
}

// ---------------- gather layer1 (fused x*dinv scaling), 16 thr/row ----------
__global__ __launch_bounds__(256) void gather1_kernel(const float* __restrict__ x) {
    int tid = blockIdx.x * 256 + threadIdx.x;
    int i = tid >> 4;
    int lane = tid & 15;
    int g = i / NN;
    int rowbase = g * NN;
    int start = d_start[i];
    int d = d_deg[i];
    const float4* xv = (const float4*)x;
    const int* cp = d_csr + (size_t)g * EE + start;
    float dvi = d_dinv[i];
    float4 self = xv[(size_t)i * 16 + lane];
    float4 acc;
    acc.x = self.x * dvi; acc.y = self.y * dvi;
    acc.z = self.z * dvi; acc.w = self.w * dvi;

    int c = 0;
    for (; c + 8 <= d; c += 8) {
#pragma unroll
        for (int jj = 0; jj < 8; jj++) {
            int sg = rowbase + __ldg(cp + c + jj);
            float ds = __ldg(d_dinv + sg);
            float4 v = xv[(size_t)sg * 16 + lane];
            acc.x = fmaf(v.x, ds, acc.x);
            acc.y = fmaf(v.y, ds, acc.y);
            acc.z = fmaf(v.z, ds, acc.z);
            acc.w = fmaf(v.w, ds, acc.w);
        }
    }
    for (; c < d; c++) {
        int sg = rowbase + __ldg(cp + c);
        float ds = __ldg(d_dinv + sg);
        float4 v = xv[(size_t)sg * 16 + lane];
        acc.x = fmaf(v.x, ds, acc.x);
        acc.y = fmaf(v.y, ds, acc.y);
        acc.z = fmaf(v.z, ds, acc.z);
        acc.w = fmaf(v.w, ds, acc.w);
    }
    acc.x *= dvi; acc.y *= dvi; acc.z *= dvi; acc.w *= dvi;
    ((float4*)d_agg)[(size_t)i * 16 + lane] = acc;
}

// =========================================================================
// fused gemm (mma.sync tf32): h2 = fp16( elu(agg@W1+b1) @ W2 * dinv )
// =========================================================================
#define FA_STRIDE 68
#define FB1_STRIDE 136
#define FA2_STRIDE 132
#define FB2_STRIDE 72
#define FB2_OFF 69632
#define FBIAS_OFF 106496
#define FUSED_SMEM 107008

__global__ __launch_bounds__(256) void fused_gemm_kernel(const float* __restrict__ W1,
                                                         const float* __restrict__ b1,
                                                         const float* __restrict__ W2) {
    extern __shared__ uint32_t smemU[];
    const uint32_t sb = smem_u32(smemU);
    uint32_t* As  = smemU;                       // stride 68 (phase 1)
    uint32_t* Bs1 = smemU + 34816 / 4;           // stride 136
    uint32_t* A2  = smemU;                       // stride 132 (phase 2, aliases)
    uint32_t* Bs2 = smemU + FB2_OFF / 4;         // stride 72
    float*    bs  = (float*)(smemU + FBIAS_OFF / 4);

    const int g = blockIdx.y;
    const int base = blockIdx.x * 128;
    const int t = threadIdx.x;
    const int w = t >> 5, lane = t & 31;
    const int gr = lane >> 2, q = lane & 3;

    if (t < HID) bs[t] = b1[g * HID + t];

    {
        const float4* Ag = (const float4*)(d_agg + ((size_t)g * NN + base) * F_IN);
        int rows = NN - base; if (rows > 128) rows = 128;
        float4 z = make_float4(0.f, 0.f, 0.f, 0.f);
        for (int i = t; i < 2048; i += 256) {
            int row = i >> 4, c4 = i & 15;
            float4 v = (row < rows) ? Ag[row * 16 + c4] : z;
            sts_tf32v4(sb + (row * FA_STRIDE + c4 * 4) * 4, v);
        }
    }
    {
        const float4* Wg = (const float4*)(W1 + (size_t)g * F_IN * HID);
        for (int i = t; i < 2048; i += 256) {
            int k = i >> 5, n4 = i & 31;
            float4 v = Wg[k * 32 + n4];
            sts_tf32v4(sb + 34816 + (k * FB1_STRIDE + n4 * 4) * 4, v);
        }
    }
    {
        const float4* Wg = (const float4*)(W2 + (size_t)g * HID * OUT);
        for (int i = t; i < 2048; i += 256) {
            int k = i >> 4, n4 = i & 15;
            float4 v = Wg[k * 16 + n4];
            sts_tf32v4(sb + FB2_OFF + (k * FB2_STRIDE + n4 * 4) * 4, v);
        }
    }
    __syncthreads();

    const int r0 = w * 16 + gr;

    float c1[16][4];
#pragma unroll
    for (int nt = 0; nt < 16; nt++) { c1[nt][0] = c1[nt][1] = c1[nt][2] = c1[nt][3] = 0.f; }
#pragma unroll
    for (int ks = 0; ks < 8; ks++) {
        int k0 = ks * 8;
        uint32_t a0 = As[r0 * FA_STRIDE + k0 + q];
        uint32_t a1 = As[(r0 + 8) * FA_STRIDE + k0 + q];
        uint32_t a2 = As[r0 * FA_STRIDE + k0 + q + 4];
        uint32_t a3 = As[(r0 + 8) * FA_STRIDE + k0 + q + 4];
#pragma unroll
        for (int nt = 0; nt < 16; nt++) {
            uint32_t b0 = Bs1[(k0 + q) * FB1_STRIDE + nt * 8 + gr];
            uint32_t b1v = Bs1[(k0 + q + 4) * FB1_STRIDE + nt * 8 + gr];
            mma8(c1[nt], a0, a1, a2, a3, b0, b1v);
        }
    }
    __syncthreads();

#pragma unroll
    for (int nt = 0; nt < 16; nt++) {
        int col = nt * 8 + 2 * q;
        float bx = bs[col], by = bs[col + 1];
        sts_tf32v2(sb + (r0 * FA2_STRIDE + col) * 4,
                   elu1(c1[nt][0] + bx), elu1(c1[nt][1] + by));
        sts_tf32v2(sb + ((r0 + 8) * FA2_STRIDE + col) * 4,
                   elu1(c1[nt][2] + bx), elu1(c1[nt][3] + by));
    }
    __syncthreads();

    float c2[8][4];
#pragma unroll
    for (int nt = 0; nt < 8; nt++) { c2[nt][0] = c2[nt][1] = c2[nt][2] = c2[nt][3] = 0.f; }
#pragma unroll
    for (int ks = 0; ks < 16; ks++) {
        int k0 = ks * 8;
        uint32_t a0 = A2[r0 * FA2_STRIDE + k0 + q];
        uint32_t a1 = A2[(r0 + 8) * FA2_STRIDE + k0 + q];
        uint32_t a2 = A2[r0 * FA2_STRIDE + k0 + q + 4];
        uint32_t a3 = A2[(r0 + 8) * FA2_STRIDE + k0 + q + 4];
#pragma unroll
        for (int nt = 0; nt < 8; nt++) {
            uint32_t b0 = Bs2[(k0 + q) * FB2_STRIDE + nt * 8 + gr];
            uint32_t b1v = Bs2[(k0 + q + 4) * FB2_STRIDE + nt * 8 + gr];
            mma8(c2[nt], a0, a1, a2, a3, b0, b1v);
        }
    }

    int row0 = base + r0, row1 = row0 + 8;
    float dv0 = (row0 < NN) ? d_dinv[g * NN + row0] : 0.f;
    float dv1 = (row1 < NN) ? d_dinv[g * NN + row1] : 0.f;
    __half* H0 = d_h2 + ((size_t)g * NN + row0) * OUT;
    __half* H1p = d_h2 + ((size_t)g * NN + row1) * OUT;
#pragma unroll
    for (int nt = 0; nt < 8; nt++) {
        int col = nt * 8 + 2 * q;
        if (row0 < NN)
            *(__half2*)(H0 + col) = __floats2half2_rn(c2[nt][0] * dv0, c2[nt][1] * dv0);
        if (row1 < NN)
            *(__half2*)(H1p + col) = __floats2half2_rn(c2[nt][2] * dv1, c2[nt][3] * dv1);
    }
}

// ---------------- gather layer2 + epilogue (fp16 rows, 8 thr/row) ----------
__global__ __launch_bounds__(256) void gather2_kernel(const float* __restrict__ b2,
                                                      float* __restrict__ out) {
    int tid = blockIdx.x * 256 + threadIdx.x;   // NTOT*8 total
    int i = tid >> 3;
    int lane = tid & 7;
    int g = i / NN;
    int rowbase = g * NN;
    int start = d_start[i];
    int d = d_deg[i];
    const uint4* hv = (const uint4*)d_h2;       // row = 8 x uint4 (64 halves)
    const int* cp = d_csr + (size_t)g * EE + start;

    float acc[8];
#pragma unroll
    for (int k = 0; k < 8; k++) acc[k] = 0.f;
    acc_half8(acc, hv[(size_t)i * 8 + lane]);   // self loop (pre-scaled)

    int c = 0;
    for (; c + 8 <= d; c += 8) {
#pragma unroll
        for (int jj = 0; jj < 8; jj++) {
            int sg = rowbase + __ldg(cp + c + jj);
            acc_half8(acc, hv[(size_t)sg * 8 + lane]);
        }
    }
    for (; c < d; c++) {
        int sg = rowbase + __ldg(cp + c);
        acc_half8(acc, hv[(size_t)sg * 8 + lane]);
    }

    float dv = d_dinv[i];
    const float4* bb = (const float4*)(b2 + g * OUT + lane * 8);
    float4 b0 = bb[0], b1 = bb[1];
    float4 r0, r1;
    r0.x = elu1(fmaf(acc[0], dv, b0.x));
    r0.y = elu1(fmaf(acc[1], dv, b0.y));
    r0.z = elu1(fmaf(acc[2], dv, b0.z));
    r0.w = elu1(fmaf(acc[3], dv, b0.w));
    r1.x = elu1(fmaf(acc[4], dv, b1.x));
    r1.y = elu1(fmaf(acc[5], dv, b1.y));
    r1.z = elu1(fmaf(acc[6], dv, b1.z));
    r1.w = elu1(fmaf(acc[7], dv, b1.w));
    float4* op = (float4*)(out + (size_t)i * OUT + lane * 8);
    op[0] = r0;
    op[1] = r1;
}

extern "C" void kernel_launch(void* const* d_in, const int* in_sizes, int n_in,
                              void* d_out, int out_size) {
    const float* x  = (const float*)d_in[0];
    const int*   ei = (const int*)  d_in[1];
    const float* W1 = (const float*)d_in[2];
    const float* b1 = (const float*)d_in[3];
    const float* W2 = (const float*)d_in[4];
    const float* b2 = (const float*)d_in[5];
    float* out = (float*)d_out;

    cudaFuncSetAttribute(fused_gemm_kernel, cudaFuncAttributeMaxDynamicSharedMemorySize, FUSED_SMEM);

    zero_deg_kernel<<<(NTOT + 255) / 256, 256>>>();
    degree_kernel<<<(G * EE + 255) / 256, 256>>>(ei);
    scan1_kernel<<<dim3(SCAN_NB_G, G), 256>>>();
    scan23_kernel<<<dim3((NN + 255) / 256, G), 256>>>();
    fill_kernel<<<(G * EE + 255) / 256, 256>>>(ei);

    gather1_kernel<<<(NTOT * 16) / 256, 256>>>(x);
    fused_gemm_kernel<<<dim3((NN + 127) / 128, G), 256, FUSED_SMEM>>>(W1, b1, W2);
    gather2_kernel<<<(NTOT * 8) / 256, 256>>>(b2, out);
}

// round 10
// speedup vs baseline: 3.7164x; 1.0923x over previous
#include <cuda_runtime.h>
#include <cuda_fp16.h>
#include <cstdint>

#define G 4
#define NN 50000
#define EE 800000
#define F_IN 64
#define HID 128
#define OUT 64
#define NTOT (G * NN)
#define SCAN_NB_G 49   // ceil(50000/1024)

// ---- scratch ----
__device__ int    d_deg   [NTOT];
__device__ int    d_scan  [NTOT];
__device__ int    d_start [NTOT];   // per-graph-relative CSR offsets
__device__ int    d_cursor[NTOT];
__device__ int    d_bsum  [G][64];
__device__ int    d_csr   [(size_t)G * EE];
__device__ float  d_dinv  [NTOT];
__device__ __half d_xh    [(size_t)NTOT * F_IN];  // fp16(x * dinv[row])
__device__ __half d_agg   [(size_t)NTOT * F_IN];  // fp16 aggregated layer-1 input
__device__ __half d_h2    [(size_t)NTOT * OUT];   // fp16 intermediate

__device__ __forceinline__ float elu1(float v) {
    return v > 0.f ? v : expm1f(v);
}

__device__ __forceinline__ uint32_t smem_u32(const void* p) {
    uint32_t a;
    asm("{ .reg .u64 t; cvta.to.shared.u64 t, %1; cvt.u32.u64 %0, t; }" : "=r"(a) : "l"(p));
    return a;
}

__device__ __forceinline__ void sts_tf32v4(uint32_t addr, float4 v) {
    uint32_t a, b, c, d;
    asm("cvt.rna.tf32.f32 %0, %1;" : "=r"(a) : "f"(v.x));
    asm("cvt.rna.tf32.f32 %0, %1;" : "=r"(b) : "f"(v.y));
    asm("cvt.rna.tf32.f32 %0, %1;" : "=r"(c) : "f"(v.z));
    asm("cvt.rna.tf32.f32 %0, %1;" : "=r"(d) : "f"(v.w));
    asm volatile("st.shared.v4.b32 [%0], {%1,%2,%3,%4};"
                 :: "r"(addr), "r"(a), "r"(b), "r"(c), "r"(d) : "memory");
}

__device__ __forceinline__ void sts_tf32v2(uint32_t addr, float x, float y) {
    uint32_t a, b;
    asm("cvt.rna.tf32.f32 %0, %1;" : "=r"(a) : "f"(x));
    asm("cvt.rna.tf32.f32 %0, %1;" : "=r"(b) : "f"(y));
    asm volatile("st.shared.v2.b32 [%0], {%1,%2};"
                 :: "r"(addr), "r"(a), "r"(b) : "memory");
}

__device__ __forceinline__ void mma8(float* c, uint32_t a0, uint32_t a1, uint32_t a2,
                                     uint32_t a3, uint32_t b0, uint32_t b1) {
    asm volatile("mma.sync.aligned.m16n8k8.row.col.f32.tf32.tf32.f32 "
                 "{%0,%1,%2,%3}, {%4,%5,%6,%7}, {%8,%9}, {%0,%1,%2,%3};"
                 : "+f"(c[0]), "+f"(c[1]), "+f"(c[2]), "+f"(c[3])
                 : "r"(a0), "r"(a1), "r"(a2), "r"(a3), "r"(b0), "r"(b1));
}

__device__ __forceinline__ void acc_half8(float* acc, uint4 v) {
    float2 p;
    p = __half22float2(*(__half2*)&v.x); acc[0] += p.x; acc[1] += p.y;
    p = __half22float2(*(__half2*)&v.y); acc[2] += p.x; acc[3] += p.y;
    p = __half22float2(*(__half2*)&v.z); acc[4] += p.x; acc[5] += p.y;
    p = __half22float2(*(__half2*)&v.w); acc[6] += p.x; acc[7] += p.y;
}

// ---------------- setup kernels ----------------
__global__ void zero_deg_kernel() {
    int i = blockIdx.x * blockDim.x + threadIdx.x;
    if (i < NTOT) d_deg[i] = 0;
}

__global__ void degree_kernel(const int* __restrict__ ei) {
    int idx = blockIdx.x * blockDim.x + threadIdx.x;
    if (idx >= G * EE) return;
    int g = idx / EE;
    int e = idx - g * EE;
    int dst = ei[(size_t)g * 2 * EE + EE + e];
    atomicAdd(&d_deg[g * NN + dst], 1);
}

// per-graph inclusive scan over 1024-node chunks; grid (49, G)
__global__ __launch_bounds__(256) void scan1_kernel() {
    __shared__ int sh[256];
    int g = blockIdx.y;
    int b = blockIdx.x, t = threadIdx.x;
    int lbase = b * 1024 + t * 4;
    int v[4]; int s = 0;
#pragma unroll
    for (int k = 0; k < 4; k++) {
        int li = lbase + k;
        v[k] = (li < NN) ? d_deg[g * NN + li] : 0;
        s += v[k];
    }
    sh[t] = s;
    __syncthreads();
    for (int off = 1; off < 256; off <<= 1) {
        int add = (t >= off) ? sh[t - off] : 0;
        __syncthreads();
        sh[t] += add;
        __syncthreads();
    }
    int run = sh[t] - s;
#pragma unroll
    for (int k = 0; k < 4; k++) {
        run += v[k];
        int li = lbase + k;
        if (li < NN) d_scan[g * NN + li] = run;
    }
    if (t == 255) d_bsum[g][b] = sh[255];
}

// fused scan2+scan3+dinv; grid ((NN+255)/256, G)
__global__ __launch_bounds__(256) void scan23_kernel() {
    __shared__ int bsh[64];
    __shared__ int boff_sh;
    int g = blockIdx.y;
    int t = threadIdx.x;
    int li = blockIdx.x * 256 + t;
    if (t < SCAN_NB_G) bsh[t] = d_bsum[g][t];
    __syncthreads();
    if (t == 0) {
        int blk = blockIdx.x >> 2;   // 256*4 = 1024 nodes per scan1 block
        int s = 0;
        for (int j = 0; j < blk; j++) s += bsh[j];
        boff_sh = s;
    }
    __syncthreads();
    if (li >= NN) return;
    int i = g * NN + li;
    int dg = d_deg[i];
    int excl = d_scan[i] - dg + boff_sh;
    d_start[i]  = excl;
    d_cursor[i] = excl;
    d_dinv[i] = rsqrtf((float)(dg + 1));
}

__global__ void fill_kernel(const int* __restrict__ ei) {
    int idx = blockIdx.x * blockDim.x + threadIdx.x;
    if (idx >= G * EE) return;
    int g = idx / EE;
    int e = idx - g * EE;
    int src = ei[(size_t)g * 2 * EE + e];
    int dst = ei[(size_t)g * 2 * EE + EE + e];
    int slot = atomicAdd(&d_cursor[g * NN + dst], 1);
    d_csr[(size_t)g * EE + slot] = src;
}

// ---------------- prescale: xh = fp16(x * dinv[row]) ----------------
__global__ void prescale_kernel(const float* __restrict__ x) {
    int tid = blockIdx.x * blockDim.x + threadIdx.x;   // NTOT*8
    int row = tid >> 3;
    int lane = tid & 7;
    float dv = d_dinv[row];
    const float4* xp = (const float4*)x + (size_t)row * 16 + lane * 2;
    float4 a = xp[0], b = xp[1];
    uint4 o;
    *(__half2*)&o.x = __floats2half2_rn(a.x * dv, a.y * dv);
    *(__half2*)&o.y = __floats2half2_rn(a.z * dv, a.w * dv);
    *(__half2*)&o.z = __floats2half2_rn(b.x * dv, b.y * dv);
    *(__half2*)&o.w = __floats2half2_rn(b.z * dv, b.w * dv);
    ((uint4*)d_xh)[(size_t)row * 8 + lane] = o;
}

// ---------------- gather layer1 (fp16 rows, 8 thr/row) ----------------
__global__ __launch_bounds__(256) void gather1_kernel() {
    int tid = blockIdx.x * 256 + threadIdx.x;   // NTOT*8
    int i = tid >> 3;
    int lane = tid & 7;
    int g = i / NN;
    int rowbase = g * NN;
    int start = d_start[i];
    int d = d_deg[i];
    const uint4* xv = (const uint4*)d_xh;
    const int* cp = d_csr + (size_t)g * EE + start;

    float acc[8];
#pragma unroll
    for (int k = 0; k < 8; k++) acc[k] = 0.f;
    acc_half8(acc, xv[(size_t)i * 8 + lane]);   // self loop (pre-scaled)

    int c = 0;
    for (; c + 8 <= d; c += 8) {
#pragma unroll
        for (int jj = 0; jj < 8; jj++) {
            int sg = rowbase + __ldg(cp + c + jj);
            acc_half8(acc, xv[(size_t)sg * 8 + lane]);
        }
    }
    for (; c < d; c++) {
        int sg = rowbase + __ldg(cp + c);
        acc_half8(acc, xv[(size_t)sg * 8 + lane]);
    }

    float dvi = d_dinv[i];
    uint4 o;
    *(__half2*)&o.x = __floats2half2_rn(acc[0] * dvi, acc[1] * dvi);
    *(__half2*)&o.y = __floats2half2_rn(acc[2] * dvi, acc[3] * dvi);
    *(__half2*)&o.z = __floats2half2_rn(acc[4] * dvi, acc[5] * dvi);
    *(__half2*)&o.w = __floats2half2_rn(acc[6] * dvi, acc[7] * dvi);
    ((uint4*)d_agg)[(size_t)i * 8 + lane] = o;
}

// =========================================================================
// fused gemm (mma.sync tf32): h2 = fp16( elu(agg@W1+b1) @ W2 * dinv )
// (agg is fp16; fp16 -> tf32 is exact, so no extra rounding here)
// =========================================================================
#define FA_STRIDE 68
#define FB1_STRIDE 136
#define FA2_STRIDE 132
#define FB2_STRIDE 72
#define FB2_OFF 69632
#define FBIAS_OFF 106496
#define FUSED_SMEM 107008

__global__ __launch_bounds__(256) void fused_gemm_kernel(const float* __restrict__ W1,
                                                         const float* __restrict__ b1,
                                                         const float* __restrict__ W2) {
    extern __shared__ uint32_t smemU[];
    const uint32_t sb = smem_u32(smemU);
    uint32_t* As  = smemU;                       // stride 68 (phase 1)
    uint32_t* Bs1 = smemU + 34816 / 4;           // stride 136
    uint32_t* A2  = smemU;                       // stride 132 (phase 2, aliases)
    uint32_t* Bs2 = smemU + FB2_OFF / 4;         // stride 72
    float*    bs  = (float*)(smemU + FBIAS_OFF / 4);

    const int g = blockIdx.y;
    const int base = blockIdx.x * 128;
    const int t = threadIdx.x;
    const int w = t >> 5, lane = t & 31;
    const int gr = lane >> 2, q = lane & 3;

    if (t < HID) bs[t] = b1[g * HID + t];

    // As fill: agg tile 128 x 64 (fp16 rows, 8 uint4 per row)
    {
        const uint4* Ag = (const uint4*)(d_agg + ((size_t)g * NN + base) * F_IN);
        int rows = NN - base; if (rows > 128) rows = 128;
        uint4 z = make_uint4(0, 0, 0, 0);
        for (int i = t; i < 1024; i += 256) {
            int row = i >> 3, c8 = i & 7;
            uint4 v = (row < rows) ? Ag[row * 8 + c8] : z;
            float2 p0 = __half22float2(*(__half2*)&v.x);
            float2 p1 = __half22float2(*(__half2*)&v.y);
            float2 p2 = __half22float2(*(__half2*)&v.z);
            float2 p3 = __half22float2(*(__half2*)&v.w);
            sts_tf32v4(sb + (row * FA_STRIDE + c8 * 8) * 4,
                       make_float4(p0.x, p0.y, p1.x, p1.y));
            sts_tf32v4(sb + (row * FA_STRIDE + c8 * 8 + 4) * 4,
                       make_float4(p2.x, p2.y, p3.x, p3.y));
        }
    }
    {
        const float4* Wg = (const float4*)(W1 + (size_t)g * F_IN * HID);
        for (int i = t; i < 2048; i += 256) {
            int k = i >> 5, n4 = i & 31;
            float4 v = Wg[k * 32 + n4];
            sts_tf32v4(sb + 34816 + (k * FB1_STRIDE + n4 * 4) * 4, v);
        }
    }
    {
        const float4* Wg = (const float4*)(W2 + (size_t)g * HID * OUT);
        for (int i = t; i < 2048; i += 256) {
            int k = i >> 4, n4 = i & 15;
            float4 v = Wg[k * 16 + n4];
            sts_tf32v4(sb + FB2_OFF + (k * FB2_STRIDE + n4 * 4) * 4, v);
        }
    }
    __syncthreads();

    const int r0 = w * 16 + gr;

    float c1[16][4];
#pragma unroll
    for (int nt = 0; nt < 16; nt++) { c1[nt][0] = c1[nt][1] = c1[nt][2] = c1[nt][3] = 0.f; }
#pragma unroll
    for (int ks = 0; ks < 8; ks++) {
        int k0 = ks * 8;
        uint32_t a0 = As[r0 * FA_STRIDE + k0 + q];
        uint32_t a1 = As[(r0 + 8) * FA_STRIDE + k0 + q];
        uint32_t a2 = As[r0 * FA_STRIDE + k0 + q + 4];
        uint32_t a3 = As[(r0 + 8) * FA_STRIDE + k0 + q + 4];
#pragma unroll
        for (int nt = 0; nt < 16; nt++) {
            uint32_t b0 = Bs1[(k0 + q) * FB1_STRIDE + nt * 8 + gr];
            uint32_t b1v = Bs1[(k0 + q + 4) * FB1_STRIDE + nt * 8 + gr];
            mma8(c1[nt], a0, a1, a2, a3, b0, b1v);
        }
    }
    __syncthreads();

#pragma unroll
    for (int nt = 0; nt < 16; nt++) {
        int col = nt * 8 + 2 * q;
        float bx = bs[col], by = bs[col + 1];
        sts_tf32v2(sb + (r0 * FA2_STRIDE + col) * 4,
                   elu1(c1[nt][0] + bx), elu1(c1[nt][1] + by));
        sts_tf32v2(sb + ((r0 + 8) * FA2_STRIDE + col) * 4,
                   elu1(c1[nt][2] + bx), elu1(c1[nt][3] + by));
    }
    __syncthreads();

    float c2[8][4];
#pragma unroll
    for (int nt = 0; nt < 8; nt++) { c2[nt][0] = c2[nt][1] = c2[nt][2] = c2[nt][3] = 0.f; }
#pragma unroll
    for (int ks = 0; ks < 16; ks++) {
        int k0 = ks * 8;
        uint32_t a0 = A2[r0 * FA2_STRIDE + k0 + q];
        uint32_t a1 = A2[(r0 + 8) * FA2_STRIDE + k0 + q];
        uint32_t a2 = A2[r0 * FA2_STRIDE + k0 + q + 4];
        uint32_t a3 = A2[(r0 + 8) * FA2_STRIDE + k0 + q + 4];
#pragma unroll
        for (int nt = 0; nt < 8; nt++) {
            uint32_t b0 = Bs2[(k0 + q) * FB2_STRIDE + nt * 8 + gr];
            uint32_t b1v = Bs2[(k0 + q + 4) * FB2_STRIDE + nt * 8 + gr];
            mma8(c2[nt], a0, a1, a2, a3, b0, b1v);
        }
    }

    int row0 = base + r0, row1 = row0 + 8;
    float dv0 = (row0 < NN) ? d_dinv[g * NN + row0] : 0.f;
    float dv1 = (row1 < NN) ? d_dinv[g * NN + row1] : 0.f;
    __half* H0 = d_h2 + ((size_t)g * NN + row0) * OUT;
    __half* H1p = d_h2 + ((size_t)g * NN + row1) * OUT;
#pragma unroll
    for (int nt = 0; nt < 8; nt++) {
        int col = nt * 8 + 2 * q;
        if (row0 < NN)
            *(__half2*)(H0 + col) = __floats2half2_rn(c2[nt][0] * dv0, c2[nt][1] * dv0);
        if (row1 < NN)
            *(__half2*)(H1p + col) = __floats2half2_rn(c2[nt][2] * dv1, c2[nt][3] * dv1);
    }
}

// ---------------- gather layer2 + epilogue (fp16 rows, 8 thr/row) ----------
__global__ __launch_bounds__(256) void gather2_kernel(const float* __restrict__ b2,
                                                      float* __restrict__ out) {
    int tid = blockIdx.x * 256 + threadIdx.x;   // NTOT*8 total
    int i = tid >> 3;
    int lane = tid & 7;
    int g = i / NN;
    int rowbase = g * NN;
    int start = d_start[i];
    int d = d_deg[i];
    const uint4* hv = (const uint4*)d_h2;       // row = 8 x uint4 (64 halves)
    const int* cp = d_csr + (size_t)g * EE + start;

    float acc[8];
#pragma unroll
    for (int k = 0; k < 8; k++) acc[k] = 0.f;
    acc_half8(acc, hv[(size_t)i * 8 + lane]);   // self loop (pre-scaled)

    int c = 0;
    for (; c + 8 <= d; c += 8) {
#pragma unroll
        for (int jj = 0; jj < 8; jj++) {
            int sg = rowbase + __ldg(cp + c + jj);
            acc_half8(acc, hv[(size_t)sg * 8 + lane]);
        }
    }
    for (; c < d; c++) {
        int sg = rowbase + __ldg(cp + c);
        acc_half8(acc, hv[(size_t)sg * 8 + lane]);
    }

    float dv = d_dinv[i];
    const float4* bb = (const float4*)(b2 + g * OUT + lane * 8);
    float4 b0 = bb[0], b1 = bb[1];
    float4 r0, r1;
    r0.x = elu1(fmaf(acc[0], dv, b0.x));
    r0.y = elu1(fmaf(acc[1], dv, b0.y));
    r0.z = elu1(fmaf(acc[2], dv, b0.z));
    r0.w = elu1(fmaf(acc[3], dv, b0.w));
    r1.x = elu1(fmaf(acc[4], dv, b1.x));
    r1.y = elu1(fmaf(acc[5], dv, b1.y));
    r1.z = elu1(fmaf(acc[6], dv, b1.z));
    r1.w = elu1(fmaf(acc[7], dv, b1.w));
    float4* op = (float4*)(out + (size_t)i * OUT + lane * 8);
    op[0] = r0;
    op[1] = r1;
}

extern "C" void kernel_launch(void* const* d_in, const int* in_sizes, int n_in,
                              void* d_out, int out_size) {
    const float* x  = (const float*)d_in[0];
    const int*   ei = (const int*)  d_in[1];
    const float* W1 = (const float*)d_in[2];
    const float* b1 = (const float*)d_in[3];
    const float* W2 = (const float*)d_in[4];
    const float* b2 = (const float*)d_in[5];
    float* out = (float*)d_out;

    cudaFuncSetAttribute(fused_gemm_kernel, cudaFuncAttributeMaxDynamicSharedMemorySize, FUSED_SMEM);

    zero_deg_kernel<<<(NTOT + 255) / 256, 256>>>();
    degree_kernel<<<(G * EE + 255) / 256, 256>>>(ei);
    scan1_kernel<<<dim3(SCAN_NB_G, G), 256>>>();
    scan23_kernel<<<dim3((NN + 255) / 256, G), 256>>>();
    fill_kernel<<<(G * EE + 255) / 256, 256>>>(ei);

    prescale_kernel<<<(NTOT * 8 + 255) / 256, 256>>>(x);
    gather1_kernel<<<(NTOT * 8) / 256, 256>>>();
    fused_gemm_kernel<<<dim3((NN + 127) / 128, G), 256, FUSED_SMEM>>>(W1, b1, W2);
    gather2_kernel<<<(NTOT * 8) / 256, 256>>>(b2, out);
}